// round 9
// baseline (speedup 1.0000x reference)
#include <cuda_runtime.h>
#include <cuda_bf16.h>
#include <cstdint>

// ===========================================================================
// Encoder (single-head attention, d=1024, batch 8, seq 2048).
// Target compiles as plain sm_100 (no 'a') -> no tcgen05/TMEM; tensor path is
// ldmatrix + mma.sync.m16n8k16 bf16 (HMMA) with bf16x3 hi/lo split:
//   A*B ~= Ahi*Bhi + Alo*Bhi + Ahi*Blo   (error ~2^-18, fp32 accum)
// All GEMMs NT.
// R9: XOR-form swizzle with precomputed row bases (1 XOR per ldmatrix addr)
//     + two-pass B (hi pass then lo pass) to cut live regs below the 128 cap
//     so ptxas can software-pipeline LDSM->HMMA chains.
// ===========================================================================

#define BATCH   8
#define SEQ     2048
#define DMODEL  1024
#define MTOT    (BATCH * SEQ)

typedef __nv_bfloat16 bf16;

// ---- static device scratch ------------------------------------------------
__device__ bf16 g_xhi [MTOT * DMODEL];
__device__ bf16 g_xlo [MTOT * DMODEL];
__device__ bf16 g_whi [4][DMODEL * DMODEL];   // q,k,v,o
__device__ bf16 g_wlo [4][DMODEL * DMODEL];
__device__ bf16 g_Qhi [MTOT * DMODEL];
__device__ bf16 g_Qlo [MTOT * DMODEL];
__device__ bf16 g_Khi [MTOT * DMODEL];
__device__ bf16 g_Klo [MTOT * DMODEL];
__device__ bf16 g_Vhi [MTOT * DMODEL];
__device__ bf16 g_Vlo [MTOT * DMODEL];
__device__ bf16 g_Vthi[MTOT * DMODEL];
__device__ bf16 g_Vtlo[MTOT * DMODEL];
__device__ float g_S  [(size_t)BATCH * SEQ * SEQ];
__device__ bf16 g_Phi [(size_t)BATCH * SEQ * SEQ];
__device__ bf16 g_Plo [(size_t)BATCH * SEQ * SEQ];
__device__ bf16 g_Chi [MTOT * DMODEL];
__device__ bf16 g_Clo [MTOT * DMODEL];

// ---- PTX helpers ----------------------------------------------------------
__device__ __forceinline__ uint32_t smem_u32(const void* p) {
    uint32_t a;
    asm("{ .reg .u64 t; cvta.to.shared.u64 t, %1; cvt.u32.u64 %0, t; }"
        : "=r"(a) : "l"(p));
    return a;
}

__device__ __forceinline__ void cp_async16(uint32_t dst, const void* src) {
    asm volatile("cp.async.cg.shared.global [%0], [%1], 16;"
                 :: "r"(dst), "l"(src) : "memory");
}
#define CP_COMMIT() asm volatile("cp.async.commit_group;" ::: "memory")
#define CP_WAIT1()  asm volatile("cp.async.wait_group 1;"  ::: "memory")
#define CP_WAIT0()  asm volatile("cp.async.wait_group 0;"  ::: "memory")

__device__ __forceinline__ void ldm_x4(uint32_t* r, uint32_t addr) {
    asm volatile("ldmatrix.sync.aligned.m8n8.x4.shared.b16 {%0,%1,%2,%3}, [%4];"
                 : "=r"(r[0]), "=r"(r[1]), "=r"(r[2]), "=r"(r[3]) : "r"(addr));
}

__device__ __forceinline__ void mma16816(float* d, const uint32_t* a,
                                         uint32_t b0, uint32_t b1) {
    asm volatile("mma.sync.aligned.m16n8k16.row.col.f32.bf16.bf16.f32 "
                 "{%0,%1,%2,%3}, {%4,%5,%6,%7}, {%8,%9}, {%0,%1,%2,%3};"
                 : "+f"(d[0]), "+f"(d[1]), "+f"(d[2]), "+f"(d[3])
                 : "r"(a[0]), "r"(a[1]), "r"(a[2]), "r"(a[3]), "r"(b0), "r"(b1));
}

__device__ __forceinline__ uint32_t pack2(bf16 a, bf16 b) {
    __nv_bfloat162 t; t.x = a; t.y = b;
    return *reinterpret_cast<uint32_t*>(&t);
}
__device__ __forceinline__ void split1(float v, bf16& hi, bf16& lo) {
    hi = __float2bfloat16_rn(v);
    lo = __float2bfloat16_rn(v - __bfloat162float(hi));
}

// ---------------------------------------------------------------------------
// hgemm: C[M,N] = alpha * A[M,K] * B[N,K]^T  in bf16x3.
// CTA tile 128x128x32, 256 threads (8 warps, 4x2, warptile 32x64),
// 3-stage cp.async pipeline (32KB/stage, 96KB total -> 2 CTAs/SM).
// 64B rows; swizzle col16' = col16 ^ ((row>>1)&3), expressed in XOR form:
//   addr(row,cb) = (tile + row*64 + (((row>>1)&3)<<4)) ^ (cb<<4)
// (bits 4-5 of the base come only from the row term, so XOR == the original
// permutation). Row bases are precomputed once per thread.
// OUTMODE 0: fp32 C (alpha applied).  OUTMODE 1: bf16 hi/lo pair.
// ---------------------------------------------------------------------------
#define GBK 32
#define STAGE_BYTES 32768
#define T_AHI 0
#define T_ALO 8192
#define T_BHI 16384
#define T_BLO 24576
#define HG_SMEM (3 * STAGE_BYTES)

template <int OUTMODE>
__global__ __launch_bounds__(256, 2)
void hgemm(const bf16* __restrict__ Ahi, const bf16* __restrict__ Alo,
           const bf16* __restrict__ Bhi, const bf16* __restrict__ Blo,
           float* __restrict__ Cf, bf16* __restrict__ Chi, bf16* __restrict__ Clo,
           int K, int ldC, float alpha,
           size_t strA, size_t strB, size_t strC)
{
    extern __shared__ __align__(128) char smem[];
    const uint32_t sb = smem_u32(smem);

    const int tid  = threadIdx.x;
    const int lane = tid & 31;
    const int wid  = tid >> 5;
    const int wm   = wid & 3;
    const int wn   = wid >> 2;

    const size_t bz = blockIdx.z;
    Ahi += bz * strA;  Alo += bz * strA;
    Bhi += bz * strB;  Blo += bz * strB;
    const int row0 = blockIdx.y * 128;
    const int col0 = blockIdx.x * 128;

    // 512 16B-chunks per tile type; 2 per thread per type.
    auto load_stage = [&](int s, int kiter) {
        const int k0 = kiter * GBK;
        const uint32_t stb = sb + s * STAGE_BYTES;
#pragma unroll
        for (int i = 0; i < 2; i++) {
            const int c    = tid + i * 256;
            const int row  = c >> 2;              // 0..127
            const int c16  = c & 3;               // 0..3 (16B col)
            const uint32_t soff =
                (uint32_t)(row * 64 + (((c16 ^ ((row >> 1) & 3)) & 3) << 4));
            const size_t goffA = (size_t)(row0 + row) * K + k0 + c16 * 8;
            const size_t goffB = (size_t)(col0 + row) * K + k0 + c16 * 8;
            cp_async16(stb + T_AHI + soff, Ahi + goffA);
            cp_async16(stb + T_ALO + soff, Alo + goffA);
            cp_async16(stb + T_BHI + soff, Bhi + goffB);
            cp_async16(stb + T_BLO + soff, Blo + goffB);
        }
    };

    const int lr16 = lane & 15;
    const int lhi  = lane >> 4;

    // precomputed swizzle row-bases (tile-relative)
    uint32_t abase[2], bbase[4];
#pragma unroll
    for (int mt = 0; mt < 2; mt++) {
        const int r = wm * 32 + mt * 16 + lr16;
        abase[mt] = (uint32_t)(r * 64 + (((r >> 1) & 3) << 4));
    }
#pragma unroll
    for (int np = 0; np < 4; np++) {
        const int r = wn * 64 + np * 16 + lr16;
        bbase[np] = (uint32_t)(r * 64 + (((r >> 1) & 3) << 4));
    }

    float acc[2][8][4];
#pragma unroll
    for (int a = 0; a < 2; a++)
#pragma unroll
        for (int b = 0; b < 8; b++)
#pragma unroll
            for (int r = 0; r < 4; r++) acc[a][b][r] = 0.f;

    const int niter = K / GBK;

    load_stage(0, 0); CP_COMMIT();
    load_stage(1, 1); CP_COMMIT();
    CP_WAIT1();
    __syncthreads();

    int s = 0, pf = 2;
    for (int it = 0; it < niter; ++it) {
        const uint32_t stb  = sb + s * STAGE_BYTES;
        const uint32_t a_hi = stb + T_AHI;
        const uint32_t a_lo = stb + T_ALO;
        const uint32_t b_hi = stb + T_BHI;
        const uint32_t b_lo = stb + T_BLO;
#pragma unroll
        for (int kk = 0; kk < 2; kk++) {
            const uint32_t xv = (uint32_t)((kk * 2 + lhi) << 4);
            uint32_t ah[2][4], al[2][4];
#pragma unroll
            for (int mt = 0; mt < 2; mt++) ldm_x4(ah[mt], (a_hi + abase[mt]) ^ xv);
#pragma unroll
            for (int mt = 0; mt < 2; mt++) ldm_x4(al[mt], (a_lo + abase[mt]) ^ xv);
            // ---- pass 1: B-hi (Ahi*Bh + Alo*Bh) ----
#pragma unroll
            for (int np = 0; np < 4; np++) {
                uint32_t bh[4];
                ldm_x4(bh, (b_hi + bbase[np]) ^ xv);
#pragma unroll
                for (int mt = 0; mt < 2; mt++) {
#pragma unroll
                    for (int sub = 0; sub < 2; sub++) {
                        float* d = acc[mt][np * 2 + sub];
                        mma16816(d, ah[mt], bh[sub], bh[sub + 2]);
                        mma16816(d, al[mt], bh[sub], bh[sub + 2]);
                    }
                }
            }
            // ---- pass 2: B-lo (Ahi*Bl) ----
#pragma unroll
            for (int np = 0; np < 4; np++) {
                uint32_t bl[4];
                ldm_x4(bl, (b_lo + bbase[np]) ^ xv);
#pragma unroll
                for (int mt = 0; mt < 2; mt++) {
#pragma unroll
                    for (int sub = 0; sub < 2; sub++) {
                        mma16816(acc[mt][np * 2 + sub], ah[mt], bl[sub], bl[sub + 2]);
                    }
                }
            }
        }
        if (it + 2 < niter) {
            load_stage(pf, it + 2);
            CP_COMMIT();
            CP_WAIT1();
        } else {
            CP_WAIT0();
        }
        __syncthreads();
        s  = (s  == 2) ? 0 : s  + 1;
        pf = (pf == 2) ? 0 : pf + 1;
    }

    const int gi = lane >> 2;
    const int ti = lane & 3;
#pragma unroll
    for (int mt = 0; mt < 2; mt++) {
#pragma unroll
        for (int nt = 0; nt < 8; nt++) {
            const int col = col0 + wn * 64 + nt * 8 + ti * 2;
#pragma unroll
            for (int h = 0; h < 2; h++) {
                const size_t row = row0 + wm * 32 + mt * 16 + gi + h * 8;
                const float v0 = acc[mt][nt][h * 2 + 0] * alpha;
                const float v1 = acc[mt][nt][h * 2 + 1] * alpha;
                const size_t off = (strC * bz) + row * ldC + col;
                if (OUTMODE == 0) {
                    float2 f2; f2.x = v0; f2.y = v1;
                    *reinterpret_cast<float2*>(Cf + off) = f2;
                } else {
                    bf16 h0, l0, h1, l1;
                    split1(v0, h0, l0);
                    split1(v1, h1, l1);
                    *reinterpret_cast<uint32_t*>(Chi + off) = pack2(h0, h1);
                    *reinterpret_cast<uint32_t*>(Clo + off) = pack2(l0, l1);
                }
            }
        }
    }
}

// ---------------------------------------------------------------------------
// split: fp32 -> bf16 hi/lo (x input; one launch)
// ---------------------------------------------------------------------------
__global__ __launch_bounds__(256)
void split_kernel(const float* __restrict__ src, bf16* __restrict__ hi,
                  bf16* __restrict__ lo, int n4)
{
    const int i = blockIdx.x * 256 + threadIdx.x;
    if (i >= n4) return;
    float4 v = reinterpret_cast<const float4*>(src)[i];
    bf16 hx, lx, hy, ly, hz, lz, hw, lw;
    split1(v.x, hx, lx); split1(v.y, hy, ly);
    split1(v.z, hz, lz); split1(v.w, hw, lw);
    uint2 ph; ph.x = pack2(hx, hy); ph.y = pack2(hz, hw);
    uint2 pl; pl.x = pack2(lx, ly); pl.y = pack2(lz, lw);
    reinterpret_cast<uint2*>(hi)[i] = ph;
    reinterpret_cast<uint2*>(lo)[i] = pl;
}

// all 4 weights in one launch: grid.z selects the weight
struct WPtrs { const float* src[4]; bf16* hi; bf16* lo; };
__global__ __launch_bounds__(256)
void split_w_kernel(WPtrs p, int n4)
{
    const int z = blockIdx.z;
    const int i = blockIdx.x * 256 + threadIdx.x;
    if (i >= n4) return;
    const size_t wstr = (size_t)DMODEL * DMODEL / 4;   // in uint2 units
    float4 v = reinterpret_cast<const float4*>(p.src[z])[i];
    bf16 hx, lx, hy, ly, hz, lz, hw, lw;
    split1(v.x, hx, lx); split1(v.y, hy, ly);
    split1(v.z, hz, lz); split1(v.w, hw, lw);
    uint2 ph; ph.x = pack2(hx, hy); ph.y = pack2(hz, hw);
    uint2 pl; pl.x = pack2(lx, ly); pl.y = pack2(lz, lw);
    reinterpret_cast<uint2*>(p.hi)[z * wstr + i] = ph;
    reinterpret_cast<uint2*>(p.lo)[z * wstr + i] = pl;
}

// ---------------------------------------------------------------------------
// bf16 transpose per batch, hi+lo in one launch: z = batch*2 + sel
// ---------------------------------------------------------------------------
__global__ __launch_bounds__(256)
void transpose_bf16(const bf16* __restrict__ srch, const bf16* __restrict__ srcl,
                    bf16* __restrict__ dsth, bf16* __restrict__ dstl)
{
    __shared__ bf16 t[32][33];
    const int b   = blockIdx.z >> 1;
    const int sel = blockIdx.z & 1;
    const bf16* s = (sel ? srcl : srch) + (size_t)b * SEQ * DMODEL;
    bf16*       o = (sel ? dstl : dsth) + (size_t)b * SEQ * DMODEL;
    const int s0 = blockIdx.x * 32;
    const int v0 = blockIdx.y * 32;
    const int tx = threadIdx.x & 31, ty = threadIdx.x >> 5;
#pragma unroll
    for (int r = 0; r < 4; r++)
        t[ty + r * 8][tx] = s[(size_t)(s0 + ty + r * 8) * DMODEL + v0 + tx];
    __syncthreads();
#pragma unroll
    for (int r = 0; r < 4; r++)
        o[(size_t)(v0 + ty + r * 8) * SEQ + s0 + tx] = t[tx][ty + r * 8];
}

// ---------------------------------------------------------------------------
// softmax row (2048) fp32 -> P bf16 hi/lo
// ---------------------------------------------------------------------------
__global__ __launch_bounds__(256)
void softmax_kernel(const float* __restrict__ S, bf16* __restrict__ Phi,
                    bf16* __restrict__ Plo)
{
    const size_t r0 = (size_t)blockIdx.x * SEQ;
    const float* row = S + r0;
    const int tid = threadIdx.x;

    float4 v0 = reinterpret_cast<const float4*>(row)[tid];
    float4 v1 = reinterpret_cast<const float4*>(row)[tid + 256];

    float m = fmaxf(fmaxf(fmaxf(v0.x, v0.y), fmaxf(v0.z, v0.w)),
                    fmaxf(fmaxf(v1.x, v1.y), fmaxf(v1.z, v1.w)));
    __shared__ float red[8];
#pragma unroll
    for (int o = 16; o > 0; o >>= 1)
        m = fmaxf(m, __shfl_xor_sync(0xffffffffu, m, o));
    if ((tid & 31) == 0) red[tid >> 5] = m;
    __syncthreads();
    m = red[0];
#pragma unroll
    for (int w = 1; w < 8; w++) m = fmaxf(m, red[w]);
    __syncthreads();

    v0.x = __expf(v0.x - m); v0.y = __expf(v0.y - m);
    v0.z = __expf(v0.z - m); v0.w = __expf(v0.w - m);
    v1.x = __expf(v1.x - m); v1.y = __expf(v1.y - m);
    v1.z = __expf(v1.z - m); v1.w = __expf(v1.w - m);

    float sum = (v0.x + v0.y + v0.z + v0.w) + (v1.x + v1.y + v1.z + v1.w);
#pragma unroll
    for (int o = 16; o > 0; o >>= 1)
        sum += __shfl_xor_sync(0xffffffffu, sum, o);
    if ((tid & 31) == 0) red[tid >> 5] = sum;
    __syncthreads();
    sum = red[0];
#pragma unroll
    for (int w = 1; w < 8; w++) sum += red[w];
    const float inv = 1.0f / sum;

    auto emit = [&](float4 v, int idx) {
        bf16 h0, l0, h1, l1, h2, l2, h3, l3;
        split1(v.x * inv, h0, l0); split1(v.y * inv, h1, l1);
        split1(v.z * inv, h2, l2); split1(v.w * inv, h3, l3);
        uint2 ph; ph.x = pack2(h0, h1); ph.y = pack2(h2, h3);
        uint2 pl; pl.x = pack2(l0, l1); pl.y = pack2(l2, l3);
        reinterpret_cast<uint2*>(Phi + r0)[idx] = ph;
        reinterpret_cast<uint2*>(Plo + r0)[idx] = pl;
    };
    emit(v0, tid);
    emit(v1, tid + 256);
}

// ---------------------------------------------------------------------------
// Launch
// ---------------------------------------------------------------------------
extern "C" void kernel_launch(void* const* d_in, const int* in_sizes, int n_in,
                              void* d_out, int out_size)
{
    const float* x  = (const float*)d_in[0];
    float* out = (float*)d_out;

    bf16 *xhi, *xlo, *whi, *wlo, *Qhi, *Qlo, *Khi, *Klo, *Vhi, *Vlo,
         *Vthi, *Vtlo, *Phi, *Plo, *Chi, *Clo;
    float* S;
    cudaGetSymbolAddress((void**)&xhi,  g_xhi);
    cudaGetSymbolAddress((void**)&xlo,  g_xlo);
    cudaGetSymbolAddress((void**)&whi,  g_whi);
    cudaGetSymbolAddress((void**)&wlo,  g_wlo);
    cudaGetSymbolAddress((void**)&Qhi,  g_Qhi);
    cudaGetSymbolAddress((void**)&Qlo,  g_Qlo);
    cudaGetSymbolAddress((void**)&Khi,  g_Khi);
    cudaGetSymbolAddress((void**)&Klo,  g_Klo);
    cudaGetSymbolAddress((void**)&Vhi,  g_Vhi);
    cudaGetSymbolAddress((void**)&Vlo,  g_Vlo);
    cudaGetSymbolAddress((void**)&Vthi, g_Vthi);
    cudaGetSymbolAddress((void**)&Vtlo, g_Vtlo);
    cudaGetSymbolAddress((void**)&S,    g_S);
    cudaGetSymbolAddress((void**)&Phi,  g_Phi);
    cudaGetSymbolAddress((void**)&Plo,  g_Plo);
    cudaGetSymbolAddress((void**)&Chi,  g_Chi);
    cudaGetSymbolAddress((void**)&Clo,  g_Clo);

    cudaFuncSetAttribute(hgemm<0>, cudaFuncAttributeMaxDynamicSharedMemorySize, HG_SMEM);
    cudaFuncSetAttribute(hgemm<1>, cudaFuncAttributeMaxDynamicSharedMemorySize, HG_SMEM);

    const dim3 blk(256);
    const size_t WSTR = (size_t)DMODEL * DMODEL;

    // #0: split x
    split_kernel<<<MTOT * DMODEL / 1024, blk>>>(x, xhi, xlo, MTOT * DMODEL / 4);

    // #1: split all 4 weights (merged launch)
    {
        WPtrs p;
        p.src[0] = (const float*)d_in[1];
        p.src[1] = (const float*)d_in[2];
        p.src[2] = (const float*)d_in[3];
        p.src[3] = (const float*)d_in[4];
        p.hi = whi; p.lo = wlo;
        dim3 g(DMODEL * DMODEL / 1024, 1, 4);
        split_w_kernel<<<g, blk>>>(p, DMODEL * DMODEL / 4);
    }

    // #2-#4: projections -> bf16 hi/lo
    {
        dim3 grid(DMODEL / 128, MTOT / 128, 1);
        hgemm<1><<<grid, blk, HG_SMEM>>>(xhi, xlo, whi + 0 * WSTR, wlo + 0 * WSTR,
                                         nullptr, Qhi, Qlo, DMODEL, DMODEL, 1.f, 0, 0, 0);
        hgemm<1><<<grid, blk, HG_SMEM>>>(xhi, xlo, whi + 1 * WSTR, wlo + 1 * WSTR,
                                         nullptr, Khi, Klo, DMODEL, DMODEL, 1.f, 0, 0, 0);
        hgemm<1><<<grid, blk, HG_SMEM>>>(xhi, xlo, whi + 2 * WSTR, wlo + 2 * WSTR,
                                         nullptr, Vhi, Vlo, DMODEL, DMODEL, 1.f, 0, 0, 0);
    }

    // #5: S = Q K^T / 32 (fp32)
    {
        dim3 grid(SEQ / 128, SEQ / 128, BATCH);
        hgemm<0><<<grid, blk, HG_SMEM>>>(Qhi, Qlo, Khi, Klo, S, nullptr, nullptr,
                                         DMODEL, SEQ, 0.03125f,
                                         (size_t)SEQ * DMODEL,
                                         (size_t)SEQ * DMODEL,
                                         (size_t)SEQ * SEQ);
    }

    // #6: V transpose (hi + lo merged)
    {
        dim3 g(SEQ / 32, DMODEL / 32, BATCH * 2);
        transpose_bf16<<<g, blk>>>(Vhi, Vlo, Vthi, Vtlo);
    }

    // #7: softmax -> P hi/lo
    softmax_kernel<<<MTOT, blk>>>(S, Phi, Plo);

    // #8: ctx = P Vt^T -> bf16 hi/lo  (K = SEQ)
    {
        dim3 grid(DMODEL / 128, SEQ / 128, BATCH);
        hgemm<1><<<grid, blk, HG_SMEM>>>(Phi, Plo, Vthi, Vtlo, nullptr, Chi, Clo,
                                         SEQ, DMODEL, 1.f,
                                         (size_t)SEQ * SEQ,
                                         (size_t)DMODEL * SEQ,
                                         (size_t)SEQ * DMODEL);
    }

    // #9: out = ctx wo^T (fp32)
    {
        dim3 grid(DMODEL / 128, MTOT / 128, 1);
        hgemm<0><<<grid, blk, HG_SMEM>>>(Chi, Clo, whi + 3 * WSTR, wlo + 3 * WSTR,
                                         out, nullptr, nullptr,
                                         DMODEL, DMODEL, 1.f, 0, 0, 0);
    }
}

// round 10
// speedup vs baseline: 1.0313x; 1.0313x over previous
#include <cuda_runtime.h>
#include <cuda_bf16.h>
#include <cstdint>

// ===========================================================================
// Encoder (single-head attention, d=1024, batch 8, seq 2048).
// Target compiles as plain sm_100 (no 'a') -> no tcgen05/TMEM; tensor path is
// ldmatrix + mma.sync.m16n8k16 bf16 (HMMA) with bf16x3 hi/lo split:
//   A*B ~= Ahi*Bhi + Alo*Bhi + Ahi*Blo   (error ~2^-18, fp32 accum)
// All GEMMs NT.
// R10: R8 core (add-form swizzle, 128x128x32 tile, 3-stage cp.async, 2
// CTAs/SM) with TERM-MAJOR MMA ordering inside each kk step: the 3 terms of
// each accumulator are 16 instructions apart (were adjacent), breaking the
// 3-deep same-accumulator HMMA chains. B frags reused hi->lo to cut regs.
// ===========================================================================

#define BATCH   8
#define SEQ     2048
#define DMODEL  1024
#define MTOT    (BATCH * SEQ)

typedef __nv_bfloat16 bf16;

// ---- static device scratch ------------------------------------------------
__device__ bf16 g_xhi [MTOT * DMODEL];
__device__ bf16 g_xlo [MTOT * DMODEL];
__device__ bf16 g_whi [4][DMODEL * DMODEL];   // q,k,v,o
__device__ bf16 g_wlo [4][DMODEL * DMODEL];
__device__ bf16 g_Qhi [MTOT * DMODEL];
__device__ bf16 g_Qlo [MTOT * DMODEL];
__device__ bf16 g_Khi [MTOT * DMODEL];
__device__ bf16 g_Klo [MTOT * DMODEL];
__device__ bf16 g_Vhi [MTOT * DMODEL];
__device__ bf16 g_Vlo [MTOT * DMODEL];
__device__ bf16 g_Vthi[MTOT * DMODEL];
__device__ bf16 g_Vtlo[MTOT * DMODEL];
__device__ float g_S  [(size_t)BATCH * SEQ * SEQ];
__device__ bf16 g_Phi [(size_t)BATCH * SEQ * SEQ];
__device__ bf16 g_Plo [(size_t)BATCH * SEQ * SEQ];
__device__ bf16 g_Chi [MTOT * DMODEL];
__device__ bf16 g_Clo [MTOT * DMODEL];

// ---- PTX helpers ----------------------------------------------------------
__device__ __forceinline__ uint32_t smem_u32(const void* p) {
    uint32_t a;
    asm("{ .reg .u64 t; cvta.to.shared.u64 t, %1; cvt.u32.u64 %0, t; }"
        : "=r"(a) : "l"(p));
    return a;
}

__device__ __forceinline__ void cp_async16(uint32_t dst, const void* src) {
    asm volatile("cp.async.cg.shared.global [%0], [%1], 16;"
                 :: "r"(dst), "l"(src) : "memory");
}
#define CP_COMMIT() asm volatile("cp.async.commit_group;" ::: "memory")
#define CP_WAIT1()  asm volatile("cp.async.wait_group 1;"  ::: "memory")
#define CP_WAIT0()  asm volatile("cp.async.wait_group 0;"  ::: "memory")

__device__ __forceinline__ void ldm_x4(uint32_t* r, uint32_t addr) {
    asm volatile("ldmatrix.sync.aligned.m8n8.x4.shared.b16 {%0,%1,%2,%3}, [%4];"
                 : "=r"(r[0]), "=r"(r[1]), "=r"(r[2]), "=r"(r[3]) : "r"(addr));
}

__device__ __forceinline__ void mma16816(float* d, const uint32_t* a,
                                         uint32_t b0, uint32_t b1) {
    asm volatile("mma.sync.aligned.m16n8k16.row.col.f32.bf16.bf16.f32 "
                 "{%0,%1,%2,%3}, {%4,%5,%6,%7}, {%8,%9}, {%0,%1,%2,%3};"
                 : "+f"(d[0]), "+f"(d[1]), "+f"(d[2]), "+f"(d[3])
                 : "r"(a[0]), "r"(a[1]), "r"(a[2]), "r"(a[3]), "r"(b0), "r"(b1));
}

__device__ __forceinline__ uint32_t pack2(bf16 a, bf16 b) {
    __nv_bfloat162 t; t.x = a; t.y = b;
    return *reinterpret_cast<uint32_t*>(&t);
}
__device__ __forceinline__ void split1(float v, bf16& hi, bf16& lo) {
    hi = __float2bfloat16_rn(v);
    lo = __float2bfloat16_rn(v - __bfloat162float(hi));
}

// ---------------------------------------------------------------------------
// hgemm: C[M,N] = alpha * A[M,K] * B[N,K]^T  in bf16x3.
// CTA tile 128x128x32, 256 threads (8 warps, 4x2, warptile 32x64),
// 3-stage cp.async pipeline (32KB/stage, 96KB total -> 2 CTAs/SM).
// 64B rows; swizzle col16' = col16 ^ ((row>>1)&3): conflict-free ldmatrix.
// OUTMODE 0: fp32 C (alpha applied).  OUTMODE 1: bf16 hi/lo pair.
// ---------------------------------------------------------------------------
#define GBK 32
#define STAGE_BYTES 32768
#define T_AHI 0
#define T_ALO 8192
#define T_BHI 16384
#define T_BLO 24576
#define HG_SMEM (3 * STAGE_BYTES)

template <int OUTMODE>
__global__ __launch_bounds__(256, 2)
void hgemm(const bf16* __restrict__ Ahi, const bf16* __restrict__ Alo,
           const bf16* __restrict__ Bhi, const bf16* __restrict__ Blo,
           float* __restrict__ Cf, bf16* __restrict__ Chi, bf16* __restrict__ Clo,
           int K, int ldC, float alpha,
           size_t strA, size_t strB, size_t strC)
{
    extern __shared__ __align__(128) char smem[];
    const uint32_t sb = smem_u32(smem);

    const int tid  = threadIdx.x;
    const int lane = tid & 31;
    const int wid  = tid >> 5;
    const int wm   = wid & 3;
    const int wn   = wid >> 2;

    const size_t bz = blockIdx.z;
    Ahi += bz * strA;  Alo += bz * strA;
    Bhi += bz * strB;  Blo += bz * strB;
    const int row0 = blockIdx.y * 128;
    const int col0 = blockIdx.x * 128;

    // 512 16B-chunks per tile type; 2 per thread per type.
    auto load_stage = [&](int s, int kiter) {
        const int k0 = kiter * GBK;
        const uint32_t stb = sb + s * STAGE_BYTES;
#pragma unroll
        for (int i = 0; i < 2; i++) {
            const int c    = tid + i * 256;
            const int row  = c >> 2;              // 0..127
            const int c16  = c & 3;               // 0..3 (16B col)
            const uint32_t soff =
                (uint32_t)(row * 64 + (((c16 ^ ((row >> 1) & 3)) & 3) << 4));
            const size_t goffA = (size_t)(row0 + row) * K + k0 + c16 * 8;
            const size_t goffB = (size_t)(col0 + row) * K + k0 + c16 * 8;
            cp_async16(stb + T_AHI + soff, Ahi + goffA);
            cp_async16(stb + T_ALO + soff, Alo + goffA);
            cp_async16(stb + T_BHI + soff, Bhi + goffB);
            cp_async16(stb + T_BLO + soff, Blo + goffB);
        }
    };

    const int lr16 = lane & 15;
    const int lhi  = lane >> 4;
    int arow[2], brow[4];
#pragma unroll
    for (int mt = 0; mt < 2; mt++) arow[mt] = wm * 32 + mt * 16 + lr16;
#pragma unroll
    for (int np = 0; np < 4; np++) brow[np] = wn * 64 + np * 16 + lr16;

    auto smaddr = [&](int row, int cb) -> uint32_t {
        return (uint32_t)(row * 64 + (((cb ^ ((row >> 1) & 3)) & 3) << 4));
    };

    float acc[2][8][4];
#pragma unroll
    for (int a = 0; a < 2; a++)
#pragma unroll
        for (int b = 0; b < 8; b++)
#pragma unroll
            for (int r = 0; r < 4; r++) acc[a][b][r] = 0.f;

    const int niter = K / GBK;

    load_stage(0, 0); CP_COMMIT();
    load_stage(1, 1); CP_COMMIT();
    CP_WAIT1();
    __syncthreads();

    int s = 0, pf = 2;
    for (int it = 0; it < niter; ++it) {
        const uint32_t stb = sb + s * STAGE_BYTES;
#pragma unroll
        for (int kk = 0; kk < 2; kk++) {
            const int cb = kk * 2 + lhi;          // 0..3
            uint32_t ah[2][4], al[2][4], b[4][4];
#pragma unroll
            for (int mt = 0; mt < 2; mt++)
                ldm_x4(ah[mt], stb + T_AHI + smaddr(arow[mt], cb));
#pragma unroll
            for (int mt = 0; mt < 2; mt++)
                ldm_x4(al[mt], stb + T_ALO + smaddr(arow[mt], cb));
#pragma unroll
            for (int np = 0; np < 4; np++)
                ldm_x4(b[np], stb + T_BHI + smaddr(brow[np], cb));
            // ---- pass 1: Ahi * Bhi (16 independent accs) ----
#pragma unroll
            for (int np = 0; np < 4; np++)
#pragma unroll
                for (int mt = 0; mt < 2; mt++)
#pragma unroll
                    for (int sub = 0; sub < 2; sub++)
                        mma16816(acc[mt][np * 2 + sub], ah[mt],
                                 b[np][sub], b[np][sub + 2]);
            // ---- pass 2: Alo * Bhi ----
#pragma unroll
            for (int np = 0; np < 4; np++)
#pragma unroll
                for (int mt = 0; mt < 2; mt++)
#pragma unroll
                    for (int sub = 0; sub < 2; sub++)
                        mma16816(acc[mt][np * 2 + sub], al[mt],
                                 b[np][sub], b[np][sub + 2]);
            // ---- reload B regs with Blo, pass 3: Ahi * Blo ----
#pragma unroll
            for (int np = 0; np < 4; np++)
                ldm_x4(b[np], stb + T_BLO + smaddr(brow[np], cb));
#pragma unroll
            for (int np = 0; np < 4; np++)
#pragma unroll
                for (int mt = 0; mt < 2; mt++)
#pragma unroll
                    for (int sub = 0; sub < 2; sub++)
                        mma16816(acc[mt][np * 2 + sub], ah[mt],
                                 b[np][sub], b[np][sub + 2]);
        }
        if (it + 2 < niter) {
            load_stage(pf, it + 2);
            CP_COMMIT();
            CP_WAIT1();
        } else {
            CP_WAIT0();
        }
        __syncthreads();
        s  = (s  == 2) ? 0 : s  + 1;
        pf = (pf == 2) ? 0 : pf + 1;
    }

    const int gi = lane >> 2;
    const int ti = lane & 3;
#pragma unroll
    for (int mt = 0; mt < 2; mt++) {
#pragma unroll
        for (int nt = 0; nt < 8; nt++) {
            const int col = col0 + wn * 64 + nt * 8 + ti * 2;
#pragma unroll
            for (int h = 0; h < 2; h++) {
                const size_t row = row0 + wm * 32 + mt * 16 + gi + h * 8;
                const float v0 = acc[mt][nt][h * 2 + 0] * alpha;
                const float v1 = acc[mt][nt][h * 2 + 1] * alpha;
                const size_t off = (strC * bz) + row * ldC + col;
                if (OUTMODE == 0) {
                    float2 f2; f2.x = v0; f2.y = v1;
                    *reinterpret_cast<float2*>(Cf + off) = f2;
                } else {
                    bf16 h0, l0, h1, l1;
                    split1(v0, h0, l0);
                    split1(v1, h1, l1);
                    *reinterpret_cast<uint32_t*>(Chi + off) = pack2(h0, h1);
                    *reinterpret_cast<uint32_t*>(Clo + off) = pack2(l0, l1);
                }
            }
        }
    }
}

// ---------------------------------------------------------------------------
// split: fp32 -> bf16 hi/lo (x input; one launch)
// ---------------------------------------------------------------------------
__global__ __launch_bounds__(256)
void split_kernel(const float* __restrict__ src, bf16* __restrict__ hi,
                  bf16* __restrict__ lo, int n4)
{
    const int i = blockIdx.x * 256 + threadIdx.x;
    if (i >= n4) return;
    float4 v = reinterpret_cast<const float4*>(src)[i];
    bf16 hx, lx, hy, ly, hz, lz, hw, lw;
    split1(v.x, hx, lx); split1(v.y, hy, ly);
    split1(v.z, hz, lz); split1(v.w, hw, lw);
    uint2 ph; ph.x = pack2(hx, hy); ph.y = pack2(hz, hw);
    uint2 pl; pl.x = pack2(lx, ly); pl.y = pack2(lz, lw);
    reinterpret_cast<uint2*>(hi)[i] = ph;
    reinterpret_cast<uint2*>(lo)[i] = pl;
}

// all 4 weights in one launch: grid.z selects the weight
struct WPtrs { const float* src[4]; bf16* hi; bf16* lo; };
__global__ __launch_bounds__(256)
void split_w_kernel(WPtrs p, int n4)
{
    const int z = blockIdx.z;
    const int i = blockIdx.x * 256 + threadIdx.x;
    if (i >= n4) return;
    const size_t wstr = (size_t)DMODEL * DMODEL / 4;   // in uint2 units
    float4 v = reinterpret_cast<const float4*>(p.src[z])[i];
    bf16 hx, lx, hy, ly, hz, lz, hw, lw;
    split1(v.x, hx, lx); split1(v.y, hy, ly);
    split1(v.z, hz, lz); split1(v.w, hw, lw);
    uint2 ph; ph.x = pack2(hx, hy); ph.y = pack2(hz, hw);
    uint2 pl; pl.x = pack2(lx, ly); pl.y = pack2(lz, lw);
    reinterpret_cast<uint2*>(p.hi)[z * wstr + i] = ph;
    reinterpret_cast<uint2*>(p.lo)[z * wstr + i] = pl;
}

// ---------------------------------------------------------------------------
// bf16 transpose per batch, hi+lo in one launch: z = batch*2 + sel
// ---------------------------------------------------------------------------
__global__ __launch_bounds__(256)
void transpose_bf16(const bf16* __restrict__ srch, const bf16* __restrict__ srcl,
                    bf16* __restrict__ dsth, bf16* __restrict__ dstl)
{
    __shared__ bf16 t[32][33];
    const int b   = blockIdx.z >> 1;
    const int sel = blockIdx.z & 1;
    const bf16* s = (sel ? srcl : srch) + (size_t)b * SEQ * DMODEL;
    bf16*       o = (sel ? dstl : dsth) + (size_t)b * SEQ * DMODEL;
    const int s0 = blockIdx.x * 32;
    const int v0 = blockIdx.y * 32;
    const int tx = threadIdx.x & 31, ty = threadIdx.x >> 5;
#pragma unroll
    for (int r = 0; r < 4; r++)
        t[ty + r * 8][tx] = s[(size_t)(s0 + ty + r * 8) * DMODEL + v0 + tx];
    __syncthreads();
#pragma unroll
    for (int r = 0; r < 4; r++)
        o[(size_t)(v0 + ty + r * 8) * SEQ + s0 + tx] = t[tx][ty + r * 8];
}

// ---------------------------------------------------------------------------
// softmax row (2048) fp32 -> P bf16 hi/lo
// ---------------------------------------------------------------------------
__global__ __launch_bounds__(256)
void softmax_kernel(const float* __restrict__ S, bf16* __restrict__ Phi,
                    bf16* __restrict__ Plo)
{
    const size_t r0 = (size_t)blockIdx.x * SEQ;
    const float* row = S + r0;
    const int tid = threadIdx.x;

    float4 v0 = reinterpret_cast<const float4*>(row)[tid];
    float4 v1 = reinterpret_cast<const float4*>(row)[tid + 256];

    float m = fmaxf(fmaxf(fmaxf(v0.x, v0.y), fmaxf(v0.z, v0.w)),
                    fmaxf(fmaxf(v1.x, v1.y), fmaxf(v1.z, v1.w)));
    __shared__ float red[8];
#pragma unroll
    for (int o = 16; o > 0; o >>= 1)
        m = fmaxf(m, __shfl_xor_sync(0xffffffffu, m, o));
    if ((tid & 31) == 0) red[tid >> 5] = m;
    __syncthreads();
    m = red[0];
#pragma unroll
    for (int w = 1; w < 8; w++) m = fmaxf(m, red[w]);
    __syncthreads();

    v0.x = __expf(v0.x - m); v0.y = __expf(v0.y - m);
    v0.z = __expf(v0.z - m); v0.w = __expf(v0.w - m);
    v1.x = __expf(v1.x - m); v1.y = __expf(v1.y - m);
    v1.z = __expf(v1.z - m); v1.w = __expf(v1.w - m);

    float sum = (v0.x + v0.y + v0.z + v0.w) + (v1.x + v1.y + v1.z + v1.w);
#pragma unroll
    for (int o = 16; o > 0; o >>= 1)
        sum += __shfl_xor_sync(0xffffffffu, sum, o);
    if ((tid & 31) == 0) red[tid >> 5] = sum;
    __syncthreads();
    sum = red[0];
#pragma unroll
    for (int w = 1; w < 8; w++) sum += red[w];
    const float inv = 1.0f / sum;

    auto emit = [&](float4 v, int idx) {
        bf16 h0, l0, h1, l1, h2, l2, h3, l3;
        split1(v.x * inv, h0, l0); split1(v.y * inv, h1, l1);
        split1(v.z * inv, h2, l2); split1(v.w * inv, h3, l3);
        uint2 ph; ph.x = pack2(h0, h1); ph.y = pack2(h2, h3);
        uint2 pl; pl.x = pack2(l0, l1); pl.y = pack2(l2, l3);
        reinterpret_cast<uint2*>(Phi + r0)[idx] = ph;
        reinterpret_cast<uint2*>(Plo + r0)[idx] = pl;
    };
    emit(v0, tid);
    emit(v1, tid + 256);
}

// ---------------------------------------------------------------------------
// Launch
// ---------------------------------------------------------------------------
extern "C" void kernel_launch(void* const* d_in, const int* in_sizes, int n_in,
                              void* d_out, int out_size)
{
    const float* x  = (const float*)d_in[0];
    float* out = (float*)d_out;

    bf16 *xhi, *xlo, *whi, *wlo, *Qhi, *Qlo, *Khi, *Klo, *Vhi, *Vlo,
         *Vthi, *Vtlo, *Phi, *Plo, *Chi, *Clo;
    float* S;
    cudaGetSymbolAddress((void**)&xhi,  g_xhi);
    cudaGetSymbolAddress((void**)&xlo,  g_xlo);
    cudaGetSymbolAddress((void**)&whi,  g_whi);
    cudaGetSymbolAddress((void**)&wlo,  g_wlo);
    cudaGetSymbolAddress((void**)&Qhi,  g_Qhi);
    cudaGetSymbolAddress((void**)&Qlo,  g_Qlo);
    cudaGetSymbolAddress((void**)&Khi,  g_Khi);
    cudaGetSymbolAddress((void**)&Klo,  g_Klo);
    cudaGetSymbolAddress((void**)&Vhi,  g_Vhi);
    cudaGetSymbolAddress((void**)&Vlo,  g_Vlo);
    cudaGetSymbolAddress((void**)&Vthi, g_Vthi);
    cudaGetSymbolAddress((void**)&Vtlo, g_Vtlo);
    cudaGetSymbolAddress((void**)&S,    g_S);
    cudaGetSymbolAddress((void**)&Phi,  g_Phi);
    cudaGetSymbolAddress((void**)&Plo,  g_Plo);
    cudaGetSymbolAddress((void**)&Chi,  g_Chi);
    cudaGetSymbolAddress((void**)&Clo,  g_Clo);

    cudaFuncSetAttribute(hgemm<0>, cudaFuncAttributeMaxDynamicSharedMemorySize, HG_SMEM);
    cudaFuncSetAttribute(hgemm<1>, cudaFuncAttributeMaxDynamicSharedMemorySize, HG_SMEM);

    const dim3 blk(256);
    const size_t WSTR = (size_t)DMODEL * DMODEL;

    // #0: split x
    split_kernel<<<MTOT * DMODEL / 1024, blk>>>(x, xhi, xlo, MTOT * DMODEL / 4);

    // #1: split all 4 weights (merged launch)
    {
        WPtrs p;
        p.src[0] = (const float*)d_in[1];
        p.src[1] = (const float*)d_in[2];
        p.src[2] = (const float*)d_in[3];
        p.src[3] = (const float*)d_in[4];
        p.hi = whi; p.lo = wlo;
        dim3 g(DMODEL * DMODEL / 1024, 1, 4);
        split_w_kernel<<<g, blk>>>(p, DMODEL * DMODEL / 4);
    }

    // #2-#4: projections -> bf16 hi/lo
    {
        dim3 grid(DMODEL / 128, MTOT / 128, 1);
        hgemm<1><<<grid, blk, HG_SMEM>>>(xhi, xlo, whi + 0 * WSTR, wlo + 0 * WSTR,
                                         nullptr, Qhi, Qlo, DMODEL, DMODEL, 1.f, 0, 0, 0);
        hgemm<1><<<grid, blk, HG_SMEM>>>(xhi, xlo, whi + 1 * WSTR, wlo + 1 * WSTR,
                                         nullptr, Khi, Klo, DMODEL, DMODEL, 1.f, 0, 0, 0);
        hgemm<1><<<grid, blk, HG_SMEM>>>(xhi, xlo, whi + 2 * WSTR, wlo + 2 * WSTR,
                                         nullptr, Vhi, Vlo, DMODEL, DMODEL, 1.f, 0, 0, 0);
    }

    // #5: S = Q K^T / 32 (fp32)
    {
        dim3 grid(SEQ / 128, SEQ / 128, BATCH);
        hgemm<0><<<grid, blk, HG_SMEM>>>(Qhi, Qlo, Khi, Klo, S, nullptr, nullptr,
                                         DMODEL, SEQ, 0.03125f,
                                         (size_t)SEQ * DMODEL,
                                         (size_t)SEQ * DMODEL,
                                         (size_t)SEQ * SEQ);
    }

    // #6: V transpose (hi + lo merged)
    {
        dim3 g(SEQ / 32, DMODEL / 32, BATCH * 2);
        transpose_bf16<<<g, blk>>>(Vhi, Vlo, Vthi, Vtlo);
    }

    // #7: softmax -> P hi/lo
    softmax_kernel<<<MTOT, blk>>>(S, Phi, Plo);

    // #8: ctx = P Vt^T -> bf16 hi/lo  (K = SEQ)
    {
        dim3 grid(DMODEL / 128, SEQ / 128, BATCH);
        hgemm<1><<<grid, blk, HG_SMEM>>>(Phi, Plo, Vthi, Vtlo, nullptr, Chi, Clo,
                                         SEQ, DMODEL, 1.f,
                                         (size_t)SEQ * SEQ,
                                         (size_t)DMODEL * SEQ,
                                         (size_t)SEQ * DMODEL);
    }

    // #9: out = ctx wo^T (fp32)
    {
        dim3 grid(DMODEL / 128, MTOT / 128, 1);
        hgemm<0><<<grid, blk, HG_SMEM>>>(Chi, Clo, whi + 3 * WSTR, wlo + 3 * WSTR,
                                         out, nullptr, nullptr,
                                         DMODEL, DMODEL, 1.f, 0, 0, 0);
    }
}

// round 12
// speedup vs baseline: 1.4612x; 1.4168x over previous
#include <cuda_runtime.h>
#include <cuda_fp16.h>
#include <cstdint>

// ===========================================================================
// Encoder (single-head attention, d=1024, batch 8, seq 2048).
// Plain sm_100 target -> no tcgen05; tensor path is ldmatrix +
// mma.sync.m16n8k16 fp16 (HMMA, fp32 accum).
// R11/R12: fp16x2 split, TWO MMA terms:  A*B ~= Ahi*B + Alo*B  with B a
// single rn-rounded fp16 tensor. Error ~2.8e-4/stage, ~7e-4 end-to-end
// (gate 1e-3). 2/3 the MMAs and 2/3 the LDSM of bf16x3.
// Core structure (swizzle, 128x128x32 tile, 3-stage cp.async, 2 CTAs/SM,
// term-major MMA ordering) is the proven R10 design.
// ===========================================================================

#define BATCH   8
#define SEQ     2048
#define DMODEL  1024
#define MTOT    (BATCH * SEQ)

typedef __half fp16;

// ---- static device scratch ------------------------------------------------
__device__ fp16 g_xhi [MTOT * DMODEL];
__device__ fp16 g_xlo [MTOT * DMODEL];
__device__ fp16 g_wh  [4][DMODEL * DMODEL];   // q,k,v,o single fp16 (B side)
__device__ fp16 g_Qhi [MTOT * DMODEL];
__device__ fp16 g_Qlo [MTOT * DMODEL];
__device__ fp16 g_Kh  [MTOT * DMODEL];
__device__ fp16 g_Vh  [MTOT * DMODEL];
__device__ fp16 g_Vth [MTOT * DMODEL];
__device__ float g_S  [(size_t)BATCH * SEQ * SEQ];
__device__ fp16 g_Phi [(size_t)BATCH * SEQ * SEQ];
__device__ fp16 g_Plo [(size_t)BATCH * SEQ * SEQ];
__device__ fp16 g_Chi [MTOT * DMODEL];
__device__ fp16 g_Clo [MTOT * DMODEL];

// ---- PTX helpers ----------------------------------------------------------
__device__ __forceinline__ uint32_t smem_u32(const void* p) {
    uint32_t a;
    asm("{ .reg .u64 t; cvta.to.shared.u64 t, %1; cvt.u32.u64 %0, t; }"
        : "=r"(a) : "l"(p));
    return a;
}

__device__ __forceinline__ void cp_async16(uint32_t dst, const void* src) {
    asm volatile("cp.async.cg.shared.global [%0], [%1], 16;"
                 :: "r"(dst), "l"(src) : "memory");
}
#define CP_COMMIT() asm volatile("cp.async.commit_group;" ::: "memory")
#define CP_WAIT1()  asm volatile("cp.async.wait_group 1;"  ::: "memory")
#define CP_WAIT0()  asm volatile("cp.async.wait_group 0;"  ::: "memory")

__device__ __forceinline__ void ldm_x4(uint32_t* r, uint32_t addr) {
    asm volatile("ldmatrix.sync.aligned.m8n8.x4.shared.b16 {%0,%1,%2,%3}, [%4];"
                 : "=r"(r[0]), "=r"(r[1]), "=r"(r[2]), "=r"(r[3]) : "r"(addr));
}

__device__ __forceinline__ void mma16816(float* d, const uint32_t* a,
                                         uint32_t b0, uint32_t b1) {
    asm volatile("mma.sync.aligned.m16n8k16.row.col.f32.f16.f16.f32 "
                 "{%0,%1,%2,%3}, {%4,%5,%6,%7}, {%8,%9}, {%0,%1,%2,%3};"
                 : "+f"(d[0]), "+f"(d[1]), "+f"(d[2]), "+f"(d[3])
                 : "r"(a[0]), "r"(a[1]), "r"(a[2]), "r"(a[3]), "r"(b0), "r"(b1));
}

__device__ __forceinline__ uint32_t pack2h(fp16 a, fp16 b) {
    __half2 t; t.x = a; t.y = b;
    return *reinterpret_cast<uint32_t*>(&t);
}
__device__ __forceinline__ void split1h(float v, fp16& hi, fp16& lo) {
    hi = __float2half_rn(v);
    lo = __float2half_rn(v - __half2float(hi));
}

// ---------------------------------------------------------------------------
// hgemm: C[M,N] = alpha * A[M,K] * B[N,K]^T, A = fp16 hi/lo, B = fp16.
// CTA tile 128x128x32, 256 threads (8 warps, 4x2, warptile 32x64),
// 3-stage cp.async pipeline (24KB/stage, 72KB total -> 2 CTAs/SM).
// 64B rows; swizzle col16' = col16 ^ ((row>>1)&3): conflict-free ldmatrix.
// OUTMODE 0: fp32 C (alpha).  1: fp16 hi/lo pair.  2: single fp16.
// ---------------------------------------------------------------------------
#define GBK 32
#define STAGE_BYTES 24576
#define T_AHI 0
#define T_ALO 8192
#define T_B   16384
#define HG_SMEM (3 * STAGE_BYTES)

template <int OUTMODE>
__global__ __launch_bounds__(256, 2)
void hgemm(const fp16* __restrict__ Ahi, const fp16* __restrict__ Alo,
           const fp16* __restrict__ B,
           float* __restrict__ Cf, fp16* __restrict__ Chi, fp16* __restrict__ Clo,
           int K, int ldC, float alpha,
           size_t strA, size_t strB, size_t strC)
{
    extern __shared__ __align__(128) char smem[];
    const uint32_t sb = smem_u32(smem);

    const int tid  = threadIdx.x;
    const int lane = tid & 31;
    const int wid  = tid >> 5;
    const int wm   = wid & 3;
    const int wn   = wid >> 2;

    const size_t bz = blockIdx.z;
    Ahi += bz * strA;  Alo += bz * strA;  B += bz * strB;
    const int row0 = blockIdx.y * 128;
    const int col0 = blockIdx.x * 128;

    // 512 16B-chunks per tile type; 2 per thread per type (3 types).
    auto load_stage = [&](int s, int kiter) {
        const int k0 = kiter * GBK;
        const uint32_t stb = sb + s * STAGE_BYTES;
#pragma unroll
        for (int i = 0; i < 2; i++) {
            const int c    = tid + i * 256;
            const int row  = c >> 2;              // 0..127
            const int c16  = c & 3;               // 0..3 (16B col)
            const uint32_t soff =
                (uint32_t)(row * 64 + (((c16 ^ ((row >> 1) & 3)) & 3) << 4));
            const size_t goffA = (size_t)(row0 + row) * K + k0 + c16 * 8;
            const size_t goffB = (size_t)(col0 + row) * K + k0 + c16 * 8;
            cp_async16(stb + T_AHI + soff, Ahi + goffA);
            cp_async16(stb + T_ALO + soff, Alo + goffA);
            cp_async16(stb + T_B   + soff, B   + goffB);
        }
    };

    const int lr16 = lane & 15;
    const int lhi  = lane >> 4;
    int arow[2], brow[4];
#pragma unroll
    for (int mt = 0; mt < 2; mt++) arow[mt] = wm * 32 + mt * 16 + lr16;
#pragma unroll
    for (int np = 0; np < 4; np++) brow[np] = wn * 64 + np * 16 + lr16;

    auto smaddr = [&](int row, int cb) -> uint32_t {
        return (uint32_t)(row * 64 + (((cb ^ ((row >> 1) & 3)) & 3) << 4));
    };

    float acc[2][8][4];
#pragma unroll
    for (int a = 0; a < 2; a++)
#pragma unroll
        for (int b = 0; b < 8; b++)
#pragma unroll
            for (int r = 0; r < 4; r++) acc[a][b][r] = 0.f;

    const int niter = K / GBK;

    load_stage(0, 0); CP_COMMIT();
    load_stage(1, 1); CP_COMMIT();
    CP_WAIT1();
    __syncthreads();

    int s = 0, pf = 2;
    for (int it = 0; it < niter; ++it) {
        const uint32_t stb = sb + s * STAGE_BYTES;
#pragma unroll
        for (int kk = 0; kk < 2; kk++) {
            const int cb = kk * 2 + lhi;          // 0..3
            uint32_t ah[2][4], al[2][4], b[4][4];
#pragma unroll
            for (int mt = 0; mt < 2; mt++)
                ldm_x4(ah[mt], stb + T_AHI + smaddr(arow[mt], cb));
#pragma unroll
            for (int mt = 0; mt < 2; mt++)
                ldm_x4(al[mt], stb + T_ALO + smaddr(arow[mt], cb));
#pragma unroll
            for (int np = 0; np < 4; np++)
                ldm_x4(b[np], stb + T_B + smaddr(brow[np], cb));
            // ---- pass 1: Ahi * B (16 independent accs) ----
#pragma unroll
            for (int np = 0; np < 4; np++)
#pragma unroll
                for (int mt = 0; mt < 2; mt++)
#pragma unroll
                    for (int sub = 0; sub < 2; sub++)
                        mma16816(acc[mt][np * 2 + sub], ah[mt],
                                 b[np][sub], b[np][sub + 2]);
            // ---- pass 2: Alo * B ----
#pragma unroll
            for (int np = 0; np < 4; np++)
#pragma unroll
                for (int mt = 0; mt < 2; mt++)
#pragma unroll
                    for (int sub = 0; sub < 2; sub++)
                        mma16816(acc[mt][np * 2 + sub], al[mt],
                                 b[np][sub], b[np][sub + 2]);
        }
        if (it + 2 < niter) {
            load_stage(pf, it + 2);
            CP_COMMIT();
            CP_WAIT1();
        } else {
            CP_WAIT0();
        }
        __syncthreads();
        s  = (s  == 2) ? 0 : s  + 1;
        pf = (pf == 2) ? 0 : pf + 1;
    }

    const int gi = lane >> 2;
    const int ti = lane & 3;
#pragma unroll
    for (int mt = 0; mt < 2; mt++) {
#pragma unroll
        for (int nt = 0; nt < 8; nt++) {
            const int col = col0 + wn * 64 + nt * 8 + ti * 2;
#pragma unroll
            for (int h = 0; h < 2; h++) {
                const size_t row = row0 + wm * 32 + mt * 16 + gi + h * 8;
                const float v0 = acc[mt][nt][h * 2 + 0] * alpha;
                const float v1 = acc[mt][nt][h * 2 + 1] * alpha;
                const size_t off = (strC * bz) + row * ldC + col;
                if (OUTMODE == 0) {
                    float2 f2; f2.x = v0; f2.y = v1;
                    *reinterpret_cast<float2*>(Cf + off) = f2;
                } else if (OUTMODE == 1) {
                    fp16 h0, l0, h1, l1;
                    split1h(v0, h0, l0);
                    split1h(v1, h1, l1);
                    *reinterpret_cast<uint32_t*>(Chi + off) = pack2h(h0, h1);
                    *reinterpret_cast<uint32_t*>(Clo + off) = pack2h(l0, l1);
                } else {
                    *reinterpret_cast<uint32_t*>(Chi + off) =
                        pack2h(__float2half_rn(v0), __float2half_rn(v1));
                }
            }
        }
    }
}

// ---------------------------------------------------------------------------
// split x: fp32 -> fp16 hi/lo
// ---------------------------------------------------------------------------
__global__ __launch_bounds__(256)
void split_kernel(const float* __restrict__ src, fp16* __restrict__ hi,
                  fp16* __restrict__ lo, int n4)
{
    const int i = blockIdx.x * 256 + threadIdx.x;
    if (i >= n4) return;
    float4 v = reinterpret_cast<const float4*>(src)[i];
    fp16 hx, lx, hy, ly, hz, lz, hw, lw;
    split1h(v.x, hx, lx); split1h(v.y, hy, ly);
    split1h(v.z, hz, lz); split1h(v.w, hw, lw);
    uint2 ph; ph.x = pack2h(hx, hy); ph.y = pack2h(hz, hw);
    uint2 pl; pl.x = pack2h(lx, ly); pl.y = pack2h(lz, lw);
    reinterpret_cast<uint2*>(hi)[i] = ph;
    reinterpret_cast<uint2*>(lo)[i] = pl;
}

// weights: fp32 -> single fp16, all 4 in one launch (grid.z selects)
struct WPtrs { const float* src[4]; fp16* h; };
__global__ __launch_bounds__(256)
void conv_w_kernel(WPtrs p, int n4)
{
    const int z = blockIdx.z;
    const int i = blockIdx.x * 256 + threadIdx.x;
    if (i >= n4) return;
    const size_t wstr = (size_t)DMODEL * DMODEL / 4;   // in uint2 units
    float4 v = reinterpret_cast<const float4*>(p.src[z])[i];
    uint2 ph;
    ph.x = pack2h(__float2half_rn(v.x), __float2half_rn(v.y));
    ph.y = pack2h(__float2half_rn(v.z), __float2half_rn(v.w));
    reinterpret_cast<uint2*>(p.h)[z * wstr + i] = ph;
}

// ---------------------------------------------------------------------------
// fp16 transpose per batch: dst[v][s] = src[s][v]
// ---------------------------------------------------------------------------
__global__ __launch_bounds__(256)
void transpose_h(const fp16* __restrict__ src, fp16* __restrict__ dst)
{
    __shared__ fp16 t[32][33];
    const fp16* s = src + (size_t)blockIdx.z * SEQ * DMODEL;
    fp16*       o = dst + (size_t)blockIdx.z * SEQ * DMODEL;
    const int s0 = blockIdx.x * 32;
    const int v0 = blockIdx.y * 32;
    const int tx = threadIdx.x & 31, ty = threadIdx.x >> 5;
#pragma unroll
    for (int r = 0; r < 4; r++)
        t[ty + r * 8][tx] = s[(size_t)(s0 + ty + r * 8) * DMODEL + v0 + tx];
    __syncthreads();
#pragma unroll
    for (int r = 0; r < 4; r++)
        o[(size_t)(v0 + ty + r * 8) * SEQ + s0 + tx] = t[tx][ty + r * 8];
}

// ---------------------------------------------------------------------------
// softmax row (2048) fp32 -> P fp16 hi/lo
// ---------------------------------------------------------------------------
__global__ __launch_bounds__(256)
void softmax_kernel(const float* __restrict__ S, fp16* __restrict__ Phi,
                    fp16* __restrict__ Plo)
{
    const size_t r0 = (size_t)blockIdx.x * SEQ;
    const float* row = S + r0;
    const int tid = threadIdx.x;

    float4 v0 = reinterpret_cast<const float4*>(row)[tid];
    float4 v1 = reinterpret_cast<const float4*>(row)[tid + 256];

    float m = fmaxf(fmaxf(fmaxf(v0.x, v0.y), fmaxf(v0.z, v0.w)),
                    fmaxf(fmaxf(v1.x, v1.y), fmaxf(v1.z, v1.w)));
    __shared__ float red[8];
#pragma unroll
    for (int o = 16; o > 0; o >>= 1)
        m = fmaxf(m, __shfl_xor_sync(0xffffffffu, m, o));
    if ((tid & 31) == 0) red[tid >> 5] = m;
    __syncthreads();
    m = red[0];
#pragma unroll
    for (int w = 1; w < 8; w++) m = fmaxf(m, red[w]);
    __syncthreads();

    v0.x = __expf(v0.x - m); v0.y = __expf(v0.y - m);
    v0.z = __expf(v0.z - m); v0.w = __expf(v0.w - m);
    v1.x = __expf(v1.x - m); v1.y = __expf(v1.y - m);
    v1.z = __expf(v1.z - m); v1.w = __expf(v1.w - m);

    float sum = (v0.x + v0.y + v0.z + v0.w) + (v1.x + v1.y + v1.z + v1.w);
#pragma unroll
    for (int o = 16; o > 0; o >>= 1)
        sum += __shfl_xor_sync(0xffffffffu, sum, o);
    if ((tid & 31) == 0) red[tid >> 5] = sum;
    __syncthreads();
    sum = red[0];
#pragma unroll
    for (int w = 1; w < 8; w++) sum += red[w];
    const float inv = 1.0f / sum;

    auto emit = [&](float4 v, int idx) {
        fp16 h0, l0, h1, l1, h2, l2, h3, l3;
        split1h(v.x * inv, h0, l0); split1h(v.y * inv, h1, l1);
        split1h(v.z * inv, h2, l2); split1h(v.w * inv, h3, l3);
        uint2 ph; ph.x = pack2h(h0, h1); ph.y = pack2h(h2, h3);
        uint2 pl; pl.x = pack2h(l0, l1); pl.y = pack2h(l2, l3);
        reinterpret_cast<uint2*>(Phi + r0)[idx] = ph;
        reinterpret_cast<uint2*>(Plo + r0)[idx] = pl;
    };
    emit(v0, tid);
    emit(v1, tid + 256);
}

// ---------------------------------------------------------------------------
// Launch
// ---------------------------------------------------------------------------
extern "C" void kernel_launch(void* const* d_in, const int* in_sizes, int n_in,
                              void* d_out, int out_size)
{
    const float* x  = (const float*)d_in[0];
    float* out = (float*)d_out;

    fp16 *xhi, *xlo, *wh, *Qhi, *Qlo, *Kh, *Vh, *Vth, *Phi, *Plo, *Chi, *Clo;
    float* S;
    cudaGetSymbolAddress((void**)&xhi, g_xhi);
    cudaGetSymbolAddress((void**)&xlo, g_xlo);
    cudaGetSymbolAddress((void**)&wh,  g_wh);
    cudaGetSymbolAddress((void**)&Qhi, g_Qhi);
    cudaGetSymbolAddress((void**)&Qlo, g_Qlo);
    cudaGetSymbolAddress((void**)&Kh,  g_Kh);
    cudaGetSymbolAddress((void**)&Vh,  g_Vh);
    cudaGetSymbolAddress((void**)&Vth, g_Vth);
    cudaGetSymbolAddress((void**)&S,   g_S);
    cudaGetSymbolAddress((void**)&Phi, g_Phi);
    cudaGetSymbolAddress((void**)&Plo, g_Plo);
    cudaGetSymbolAddress((void**)&Chi, g_Chi);
    cudaGetSymbolAddress((void**)&Clo, g_Clo);

    cudaFuncSetAttribute(hgemm<0>, cudaFuncAttributeMaxDynamicSharedMemorySize, HG_SMEM);
    cudaFuncSetAttribute(hgemm<1>, cudaFuncAttributeMaxDynamicSharedMemorySize, HG_SMEM);
    cudaFuncSetAttribute(hgemm<2>, cudaFuncAttributeMaxDynamicSharedMemorySize, HG_SMEM);

    const dim3 blk(256);
    const size_t WSTR = (size_t)DMODEL * DMODEL;

    // #0: split x -> fp16 hi/lo
    split_kernel<<<MTOT * DMODEL / 1024, blk>>>(x, xhi, xlo, MTOT * DMODEL / 4);

    // #1: convert all 4 weights -> single fp16
    {
        WPtrs p;
        p.src[0] = (const float*)d_in[1];
        p.src[1] = (const float*)d_in[2];
        p.src[2] = (const float*)d_in[3];
        p.src[3] = (const float*)d_in[4];
        p.h = wh;
        dim3 g(DMODEL * DMODEL / 1024, 1, 4);
        conv_w_kernel<<<g, blk>>>(p, DMODEL * DMODEL / 4);
    }

    // #2-#4: projections. Q -> hi/lo (A side later); K,V -> single fp16.
    {
        dim3 grid(DMODEL / 128, MTOT / 128, 1);
        hgemm<1><<<grid, blk, HG_SMEM>>>(xhi, xlo, wh + 0 * WSTR,
                                         nullptr, Qhi, Qlo, DMODEL, DMODEL, 1.f, 0, 0, 0);
        hgemm<2><<<grid, blk, HG_SMEM>>>(xhi, xlo, wh + 1 * WSTR,
                                         nullptr, Kh, nullptr, DMODEL, DMODEL, 1.f, 0, 0, 0);
        hgemm<2><<<grid, blk, HG_SMEM>>>(xhi, xlo, wh + 2 * WSTR,
                                         nullptr, Vh, nullptr, DMODEL, DMODEL, 1.f, 0, 0, 0);
    }

    // #5: S = Q K^T / 32 (fp32)
    {
        dim3 grid(SEQ / 128, SEQ / 128, BATCH);
        hgemm<0><<<grid, blk, HG_SMEM>>>(Qhi, Qlo, Kh, S, nullptr, nullptr,
                                         DMODEL, SEQ, 0.03125f,
                                         (size_t)SEQ * DMODEL,
                                         (size_t)SEQ * DMODEL,
                                         (size_t)SEQ * SEQ);
    }

    // #6: V transpose (single fp16)
    {
        dim3 g(SEQ / 32, DMODEL / 32, BATCH);
        transpose_h<<<g, blk>>>(Vh, Vth);
    }

    // #7: softmax -> P fp16 hi/lo
    softmax_kernel<<<MTOT, blk>>>(S, Phi, Plo);

    // #8: ctx = P Vt^T -> fp16 hi/lo  (K = SEQ)
    {
        dim3 grid(DMODEL / 128, SEQ / 128, BATCH);
        hgemm<1><<<grid, blk, HG_SMEM>>>(Phi, Plo, Vth, nullptr, Chi, Clo,
                                         SEQ, DMODEL, 1.f,
                                         (size_t)SEQ * SEQ,
                                         (size_t)DMODEL * SEQ,
                                         (size_t)SEQ * DMODEL);
    }

    // #9: out = ctx wo^T (fp32)
    {
        dim3 grid(DMODEL / 128, MTOT / 128, 1);
        hgemm<0><<<grid, blk, HG_SMEM>>>(Chi, Clo, wh + 3 * WSTR,
                                         out, nullptr, nullptr,
                                         DMODEL, DMODEL, 1.f, 0, 0, 0);
    }
}

// round 13
// speedup vs baseline: 2.0385x; 1.3951x over previous
#include <cuda_runtime.h>
#include <cuda_fp16.h>
#include <cstdint>

// ===========================================================================
// Encoder (single-head attention, d=1024, batch 8, seq 2048).
// Plain sm_100 target -> no tcgen05; tensor path is ldmatrix +
// mma.sync.m16n8k16 fp16 (HMMA, fp32 accum).
// R13: calibrated-precision term allocation (2e-4 per single-fp16 rounding,
// measured R12):
//   projections: x(hi/lo) x W(fp16)   -> 2-term   (precision anchor)
//   S   = Q(fp16) K^T(fp16)           -> 1-term
//   ctx = P(fp16) Vt^T(fp16)          -> 1-term
//   out = ctx(fp16) wo^T(fp16)        -> 1-term
// Predicted rel_err ~5.3e-4 (gate 1e-3). GEMM units drop 1648 -> 1133 us.
// Core structure (swizzle, 128x128x32 tile, 3-stage cp.async, 2 CTAs/SM,
// term-major MMA ordering) is the proven R10/R12 design.
// ===========================================================================

#define BATCH   8
#define SEQ     2048
#define DMODEL  1024
#define MTOT    (BATCH * SEQ)

typedef __half fp16;

// ---- static device scratch ------------------------------------------------
__device__ fp16 g_xhi [MTOT * DMODEL];
__device__ fp16 g_xlo [MTOT * DMODEL];
__device__ fp16 g_wh  [4][DMODEL * DMODEL];   // q,k,v,o single fp16 (B side)
__device__ fp16 g_Qh  [MTOT * DMODEL];
__device__ fp16 g_Kh  [MTOT * DMODEL];
__device__ fp16 g_Vh  [MTOT * DMODEL];
__device__ fp16 g_Vth [MTOT * DMODEL];
__device__ float g_S  [(size_t)BATCH * SEQ * SEQ];
__device__ fp16 g_Ph  [(size_t)BATCH * SEQ * SEQ];
__device__ fp16 g_Ch  [MTOT * DMODEL];

// ---- PTX helpers ----------------------------------------------------------
__device__ __forceinline__ uint32_t smem_u32(const void* p) {
    uint32_t a;
    asm("{ .reg .u64 t; cvta.to.shared.u64 t, %1; cvt.u32.u64 %0, t; }"
        : "=r"(a) : "l"(p));
    return a;
}

__device__ __forceinline__ void cp_async16(uint32_t dst, const void* src) {
    asm volatile("cp.async.cg.shared.global [%0], [%1], 16;"
                 :: "r"(dst), "l"(src) : "memory");
}
#define CP_COMMIT() asm volatile("cp.async.commit_group;" ::: "memory")
#define CP_WAIT1()  asm volatile("cp.async.wait_group 1;"  ::: "memory")
#define CP_WAIT0()  asm volatile("cp.async.wait_group 0;"  ::: "memory")

__device__ __forceinline__ void ldm_x4(uint32_t* r, uint32_t addr) {
    asm volatile("ldmatrix.sync.aligned.m8n8.x4.shared.b16 {%0,%1,%2,%3}, [%4];"
                 : "=r"(r[0]), "=r"(r[1]), "=r"(r[2]), "=r"(r[3]) : "r"(addr));
}

__device__ __forceinline__ void mma16816(float* d, const uint32_t* a,
                                         uint32_t b0, uint32_t b1) {
    asm volatile("mma.sync.aligned.m16n8k16.row.col.f32.f16.f16.f32 "
                 "{%0,%1,%2,%3}, {%4,%5,%6,%7}, {%8,%9}, {%0,%1,%2,%3};"
                 : "+f"(d[0]), "+f"(d[1]), "+f"(d[2]), "+f"(d[3])
                 : "r"(a[0]), "r"(a[1]), "r"(a[2]), "r"(a[3]), "r"(b0), "r"(b1));
}

__device__ __forceinline__ uint32_t pack2h(fp16 a, fp16 b) {
    __half2 t; t.x = a; t.y = b;
    return *reinterpret_cast<uint32_t*>(&t);
}
__device__ __forceinline__ void split1h(float v, fp16& hi, fp16& lo) {
    hi = __float2half_rn(v);
    lo = __float2half_rn(v - __half2float(hi));
}

// ---------------------------------------------------------------------------
// hgemm<OUTMODE, TERMS>: C[M,N] = alpha * A[M,K] * B[N,K]^T
//   TERMS=2: A = fp16 hi/lo (2 MMA passes).  TERMS=1: A = single fp16.
//   OUTMODE 0: fp32 C (alpha applied).  OUTMODE 2: single fp16 C.
// CTA tile 128x128x32, 256 threads (8 warps, 4x2, warptile 32x64),
// 3-stage cp.async pipeline; stage = 24KB (TERMS=2) or 16KB (TERMS=1).
// 64B rows; swizzle col16' = col16 ^ ((row>>1)&3): conflict-free ldmatrix.
// ---------------------------------------------------------------------------
#define GBK 32

template <int OUTMODE, int TERMS>
__global__ __launch_bounds__(256, 2)
void hgemm(const fp16* __restrict__ Ahi, const fp16* __restrict__ Alo,
           const fp16* __restrict__ B,
           float* __restrict__ Cf, fp16* __restrict__ Ch,
           int K, int ldC, float alpha,
           size_t strA, size_t strB, size_t strC)
{
    constexpr int STAGE_BYTES = (TERMS == 2) ? 24576 : 16384;
    constexpr int T_ALO = 8192;
    constexpr int T_B   = (TERMS == 2) ? 16384 : 8192;

    extern __shared__ __align__(128) char smem[];
    const uint32_t sb = smem_u32(smem);

    const int tid  = threadIdx.x;
    const int lane = tid & 31;
    const int wid  = tid >> 5;
    const int wm   = wid & 3;
    const int wn   = wid >> 2;

    const size_t bz = blockIdx.z;
    Ahi += bz * strA;
    if (TERMS == 2) Alo += bz * strA;
    B += bz * strB;
    const int row0 = blockIdx.y * 128;
    const int col0 = blockIdx.x * 128;

    // 512 16B-chunks per tile type; 2 per thread per type.
    auto load_stage = [&](int s, int kiter) {
        const int k0 = kiter * GBK;
        const uint32_t stb = sb + s * STAGE_BYTES;
#pragma unroll
        for (int i = 0; i < 2; i++) {
            const int c    = tid + i * 256;
            const int row  = c >> 2;              // 0..127
            const int c16  = c & 3;               // 0..3 (16B col)
            const uint32_t soff =
                (uint32_t)(row * 64 + (((c16 ^ ((row >> 1) & 3)) & 3) << 4));
            const size_t goffA = (size_t)(row0 + row) * K + k0 + c16 * 8;
            const size_t goffB = (size_t)(col0 + row) * K + k0 + c16 * 8;
            cp_async16(stb + soff, Ahi + goffA);
            if (TERMS == 2) cp_async16(stb + T_ALO + soff, Alo + goffA);
            cp_async16(stb + T_B + soff, B + goffB);
        }
    };

    const int lr16 = lane & 15;
    const int lhi  = lane >> 4;
    int arow[2], brow[4];
#pragma unroll
    for (int mt = 0; mt < 2; mt++) arow[mt] = wm * 32 + mt * 16 + lr16;
#pragma unroll
    for (int np = 0; np < 4; np++) brow[np] = wn * 64 + np * 16 + lr16;

    auto smaddr = [&](int row, int cb) -> uint32_t {
        return (uint32_t)(row * 64 + (((cb ^ ((row >> 1) & 3)) & 3) << 4));
    };

    float acc[2][8][4];
#pragma unroll
    for (int a = 0; a < 2; a++)
#pragma unroll
        for (int b = 0; b < 8; b++)
#pragma unroll
            for (int r = 0; r < 4; r++) acc[a][b][r] = 0.f;

    const int niter = K / GBK;

    load_stage(0, 0); CP_COMMIT();
    load_stage(1, 1); CP_COMMIT();
    CP_WAIT1();
    __syncthreads();

    int s = 0, pf = 2;
    for (int it = 0; it < niter; ++it) {
        const uint32_t stb = sb + s * STAGE_BYTES;
#pragma unroll
        for (int kk = 0; kk < 2; kk++) {
            const int cb = kk * 2 + lhi;          // 0..3
            uint32_t ah[2][4], al[2][4], b[4][4];
#pragma unroll
            for (int mt = 0; mt < 2; mt++)
                ldm_x4(ah[mt], stb + smaddr(arow[mt], cb));
            if (TERMS == 2) {
#pragma unroll
                for (int mt = 0; mt < 2; mt++)
                    ldm_x4(al[mt], stb + T_ALO + smaddr(arow[mt], cb));
            }
#pragma unroll
            for (int np = 0; np < 4; np++)
                ldm_x4(b[np], stb + T_B + smaddr(brow[np], cb));
            // ---- pass 1: Ahi * B ----
#pragma unroll
            for (int np = 0; np < 4; np++)
#pragma unroll
                for (int mt = 0; mt < 2; mt++)
#pragma unroll
                    for (int sub = 0; sub < 2; sub++)
                        mma16816(acc[mt][np * 2 + sub], ah[mt],
                                 b[np][sub], b[np][sub + 2]);
            // ---- pass 2: Alo * B ----
            if (TERMS == 2) {
#pragma unroll
                for (int np = 0; np < 4; np++)
#pragma unroll
                    for (int mt = 0; mt < 2; mt++)
#pragma unroll
                        for (int sub = 0; sub < 2; sub++)
                            mma16816(acc[mt][np * 2 + sub], al[mt],
                                     b[np][sub], b[np][sub + 2]);
            }
        }
        if (it + 2 < niter) {
            load_stage(pf, it + 2);
            CP_COMMIT();
            CP_WAIT1();
        } else {
            CP_WAIT0();
        }
        __syncthreads();
        s  = (s  == 2) ? 0 : s  + 1;
        pf = (pf == 2) ? 0 : pf + 1;
    }

    const int gi = lane >> 2;
    const int ti = lane & 3;
#pragma unroll
    for (int mt = 0; mt < 2; mt++) {
#pragma unroll
        for (int nt = 0; nt < 8; nt++) {
            const int col = col0 + wn * 64 + nt * 8 + ti * 2;
#pragma unroll
            for (int h = 0; h < 2; h++) {
                const size_t row = row0 + wm * 32 + mt * 16 + gi + h * 8;
                const float v0 = acc[mt][nt][h * 2 + 0] * alpha;
                const float v1 = acc[mt][nt][h * 2 + 1] * alpha;
                const size_t off = (strC * bz) + row * ldC + col;
                if (OUTMODE == 0) {
                    float2 f2; f2.x = v0; f2.y = v1;
                    *reinterpret_cast<float2*>(Cf + off) = f2;
                } else {
                    *reinterpret_cast<uint32_t*>(Ch + off) =
                        pack2h(__float2half_rn(v0), __float2half_rn(v1));
                }
            }
        }
    }
}

#define SMEM_T2 (3 * 24576)
#define SMEM_T1 (3 * 16384)

// ---------------------------------------------------------------------------
// split x: fp32 -> fp16 hi/lo
// ---------------------------------------------------------------------------
__global__ __launch_bounds__(256)
void split_kernel(const float* __restrict__ src, fp16* __restrict__ hi,
                  fp16* __restrict__ lo, int n4)
{
    const int i = blockIdx.x * 256 + threadIdx.x;
    if (i >= n4) return;
    float4 v = reinterpret_cast<const float4*>(src)[i];
    fp16 hx, lx, hy, ly, hz, lz, hw, lw;
    split1h(v.x, hx, lx); split1h(v.y, hy, ly);
    split1h(v.z, hz, lz); split1h(v.w, hw, lw);
    uint2 ph; ph.x = pack2h(hx, hy); ph.y = pack2h(hz, hw);
    uint2 pl; pl.x = pack2h(lx, ly); pl.y = pack2h(lz, lw);
    reinterpret_cast<uint2*>(hi)[i] = ph;
    reinterpret_cast<uint2*>(lo)[i] = pl;
}

// weights: fp32 -> single fp16, all 4 in one launch (grid.z selects)
struct WPtrs { const float* src[4]; fp16* h; };
__global__ __launch_bounds__(256)
void conv_w_kernel(WPtrs p, int n4)
{
    const int z = blockIdx.z;
    const int i = blockIdx.x * 256 + threadIdx.x;
    if (i >= n4) return;
    const size_t wstr = (size_t)DMODEL * DMODEL / 4;   // in uint2 units
    float4 v = reinterpret_cast<const float4*>(p.src[z])[i];
    uint2 ph;
    ph.x = pack2h(__float2half_rn(v.x), __float2half_rn(v.y));
    ph.y = pack2h(__float2half_rn(v.z), __float2half_rn(v.w));
    reinterpret_cast<uint2*>(p.h)[z * wstr + i] = ph;
}

// ---------------------------------------------------------------------------
// fp16 transpose per batch: dst[v][s] = src[s][v]
// ---------------------------------------------------------------------------
__global__ __launch_bounds__(256)
void transpose_h(const fp16* __restrict__ src, fp16* __restrict__ dst)
{
    __shared__ fp16 t[32][33];
    const fp16* s = src + (size_t)blockIdx.z * SEQ * DMODEL;
    fp16*       o = dst + (size_t)blockIdx.z * SEQ * DMODEL;
    const int s0 = blockIdx.x * 32;
    const int v0 = blockIdx.y * 32;
    const int tx = threadIdx.x & 31, ty = threadIdx.x >> 5;
#pragma unroll
    for (int r = 0; r < 4; r++)
        t[ty + r * 8][tx] = s[(size_t)(s0 + ty + r * 8) * DMODEL + v0 + tx];
    __syncthreads();
#pragma unroll
    for (int r = 0; r < 4; r++)
        o[(size_t)(v0 + ty + r * 8) * SEQ + s0 + tx] = t[tx][ty + r * 8];
}

// ---------------------------------------------------------------------------
// softmax row (2048) fp32 -> P single fp16
// ---------------------------------------------------------------------------
__global__ __launch_bounds__(256)
void softmax_kernel(const float* __restrict__ S, fp16* __restrict__ Ph)
{
    const size_t r0 = (size_t)blockIdx.x * SEQ;
    const float* row = S + r0;
    const int tid = threadIdx.x;

    float4 v0 = reinterpret_cast<const float4*>(row)[tid];
    float4 v1 = reinterpret_cast<const float4*>(row)[tid + 256];

    float m = fmaxf(fmaxf(fmaxf(v0.x, v0.y), fmaxf(v0.z, v0.w)),
                    fmaxf(fmaxf(v1.x, v1.y), fmaxf(v1.z, v1.w)));
    __shared__ float red[8];
#pragma unroll
    for (int o = 16; o > 0; o >>= 1)
        m = fmaxf(m, __shfl_xor_sync(0xffffffffu, m, o));
    if ((tid & 31) == 0) red[tid >> 5] = m;
    __syncthreads();
    m = red[0];
#pragma unroll
    for (int w = 1; w < 8; w++) m = fmaxf(m, red[w]);
    __syncthreads();

    v0.x = __expf(v0.x - m); v0.y = __expf(v0.y - m);
    v0.z = __expf(v0.z - m); v0.w = __expf(v0.w - m);
    v1.x = __expf(v1.x - m); v1.y = __expf(v1.y - m);
    v1.z = __expf(v1.z - m); v1.w = __expf(v1.w - m);

    float sum = (v0.x + v0.y + v0.z + v0.w) + (v1.x + v1.y + v1.z + v1.w);
#pragma unroll
    for (int o = 16; o > 0; o >>= 1)
        sum += __shfl_xor_sync(0xffffffffu, sum, o);
    if ((tid & 31) == 0) red[tid >> 5] = sum;
    __syncthreads();
    sum = red[0];
#pragma unroll
    for (int w = 1; w < 8; w++) sum += red[w];
    const float inv = 1.0f / sum;

    auto emit = [&](float4 v, int idx) {
        uint2 ph;
        ph.x = pack2h(__float2half_rn(v.x * inv), __float2half_rn(v.y * inv));
        ph.y = pack2h(__float2half_rn(v.z * inv), __float2half_rn(v.w * inv));
        reinterpret_cast<uint2*>(Ph + r0)[idx] = ph;
    };
    emit(v0, tid);
    emit(v1, tid + 256);
}

// ---------------------------------------------------------------------------
// Launch
// ---------------------------------------------------------------------------
extern "C" void kernel_launch(void* const* d_in, const int* in_sizes, int n_in,
                              void* d_out, int out_size)
{
    const float* x  = (const float*)d_in[0];
    float* out = (float*)d_out;

    fp16 *xhi, *xlo, *wh, *Qh, *Kh, *Vh, *Vth, *Ph, *Ch;
    float* S;
    cudaGetSymbolAddress((void**)&xhi, g_xhi);
    cudaGetSymbolAddress((void**)&xlo, g_xlo);
    cudaGetSymbolAddress((void**)&wh,  g_wh);
    cudaGetSymbolAddress((void**)&Qh,  g_Qh);
    cudaGetSymbolAddress((void**)&Kh,  g_Kh);
    cudaGetSymbolAddress((void**)&Vh,  g_Vh);
    cudaGetSymbolAddress((void**)&Vth, g_Vth);
    cudaGetSymbolAddress((void**)&S,   g_S);
    cudaGetSymbolAddress((void**)&Ph,  g_Ph);
    cudaGetSymbolAddress((void**)&Ch,  g_Ch);

    cudaFuncSetAttribute(hgemm<2, 2>, cudaFuncAttributeMaxDynamicSharedMemorySize, SMEM_T2);
    cudaFuncSetAttribute(hgemm<0, 1>, cudaFuncAttributeMaxDynamicSharedMemorySize, SMEM_T1);
    cudaFuncSetAttribute(hgemm<2, 1>, cudaFuncAttributeMaxDynamicSharedMemorySize, SMEM_T1);

    const dim3 blk(256);
    const size_t WSTR = (size_t)DMODEL * DMODEL;

    // #0: split x -> fp16 hi/lo
    split_kernel<<<MTOT * DMODEL / 1024, blk>>>(x, xhi, xlo, MTOT * DMODEL / 4);

    // #1: convert all 4 weights -> single fp16
    {
        WPtrs p;
        p.src[0] = (const float*)d_in[1];
        p.src[1] = (const float*)d_in[2];
        p.src[2] = (const float*)d_in[3];
        p.src[3] = (const float*)d_in[4];
        p.h = wh;
        dim3 g(DMODEL * DMODEL / 1024, 1, 4);
        conv_w_kernel<<<g, blk>>>(p, DMODEL * DMODEL / 4);
    }

    // #2-#4: projections (2-term) -> single fp16 Q/K/V
    {
        dim3 grid(DMODEL / 128, MTOT / 128, 1);
        hgemm<2, 2><<<grid, blk, SMEM_T2>>>(xhi, xlo, wh + 0 * WSTR,
                                            nullptr, Qh, DMODEL, DMODEL, 1.f, 0, 0, 0);
        hgemm<2, 2><<<grid, blk, SMEM_T2>>>(xhi, xlo, wh + 1 * WSTR,
                                            nullptr, Kh, DMODEL, DMODEL, 1.f, 0, 0, 0);
        hgemm<2, 2><<<grid, blk, SMEM_T2>>>(xhi, xlo, wh + 2 * WSTR,
                                            nullptr, Vh, DMODEL, DMODEL, 1.f, 0, 0, 0);
    }

    // #5: S = Q K^T / 32 (fp32, 1-term)
    {
        dim3 grid(SEQ / 128, SEQ / 128, BATCH);
        hgemm<0, 1><<<grid, blk, SMEM_T1>>>(Qh, nullptr, Kh, S, nullptr,
                                            DMODEL, SEQ, 0.03125f,
                                            (size_t)SEQ * DMODEL,
                                            (size_t)SEQ * DMODEL,
                                            (size_t)SEQ * SEQ);
    }

    // #6: V transpose
    {
        dim3 g(SEQ / 32, DMODEL / 32, BATCH);
        transpose_h<<<g, blk>>>(Vh, Vth);
    }

    // #7: softmax -> P single fp16
    softmax_kernel<<<MTOT, blk>>>(S, Ph);

    // #8: ctx = P Vt^T (1-term) -> single fp16
    {
        dim3 grid(DMODEL / 128, SEQ / 128, BATCH);
        hgemm<2, 1><<<grid, blk, SMEM_T1>>>(Ph, nullptr, Vth, nullptr, Ch,
                                            SEQ, DMODEL, 1.f,
                                            (size_t)SEQ * SEQ,
                                            (size_t)DMODEL * SEQ,
                                            (size_t)SEQ * DMODEL);
    }

    // #9: out = ctx wo^T (fp32, 1-term)
    {
        dim3 grid(DMODEL / 128, MTOT / 128, 1);
        hgemm<0, 1><<<grid, blk, SMEM_T1>>>(Ch, nullptr, wh + 3 * WSTR,
                                            out, nullptr,
                                            DMODEL, DMODEL, 1.f, 0, 0, 0);
    }
}

// round 15
// speedup vs baseline: 2.5962x; 1.2736x over previous
#include <cuda_runtime.h>
#include <cuda_fp16.h>
#include <cstdint>

// ===========================================================================
// Encoder (single-head attention, d=1024, batch 8, seq 2048).
// Plain sm_100 target -> no tcgen05; tensor path is ldmatrix +
// mma.sync.m16n8k16 fp16 (HMMA, fp32 accum).
// R14/R15: fully 1-term fp16 pipeline. Calibrated error model (2-2.8e-4 per
// single-fp16 rounding, incoherent): roundings = {W, x, Q, K, V, P, ctx}
// -> predicted rel_err ~6.4e-4 (gate 1e-3; measured 5.0e-4 before x-rounding).
//   proj: x(fp16) W^T(fp16)   S: Q K^T /32 (fp32 out)
//   ctx:  P(fp16) Vt^T        out: ctx wo^T (fp32 out)
// GEMM units 1133 -> 824 us-equiv at the measured 64%-tensor rate.
// Core structure (swizzle, 128x128x32 tile, 3-stage cp.async, 2 CTAs/SM,
// term-major MMA ordering) is the proven R10/R12/R13 design.
// ===========================================================================

#define BATCH   8
#define SEQ     2048
#define DMODEL  1024
#define MTOT    (BATCH * SEQ)

typedef __half fp16;

// ---- static device scratch ------------------------------------------------
__device__ fp16 g_xh  [MTOT * DMODEL];
__device__ fp16 g_wh  [4][DMODEL * DMODEL];   // q,k,v,o single fp16
__device__ fp16 g_Qh  [MTOT * DMODEL];
__device__ fp16 g_Kh  [MTOT * DMODEL];
__device__ fp16 g_Vh  [MTOT * DMODEL];
__device__ fp16 g_Vth [MTOT * DMODEL];
__device__ float g_S  [(size_t)BATCH * SEQ * SEQ];
__device__ fp16 g_Ph  [(size_t)BATCH * SEQ * SEQ];
__device__ fp16 g_Ch  [MTOT * DMODEL];

// ---- PTX helpers ----------------------------------------------------------
__device__ __forceinline__ uint32_t smem_u32(const void* p) {
    uint32_t a;
    asm("{ .reg .u64 t; cvta.to.shared.u64 t, %1; cvt.u32.u64 %0, t; }"
        : "=r"(a) : "l"(p));
    return a;
}

__device__ __forceinline__ void cp_async16(uint32_t dst, const void* src) {
    asm volatile("cp.async.cg.shared.global [%0], [%1], 16;"
                 :: "r"(dst), "l"(src) : "memory");
}
#define CP_COMMIT() asm volatile("cp.async.commit_group;" ::: "memory")
#define CP_WAIT1()  asm volatile("cp.async.wait_group 1;"  ::: "memory")
#define CP_WAIT0()  asm volatile("cp.async.wait_group 0;"  ::: "memory")

__device__ __forceinline__ void ldm_x4(uint32_t* r, uint32_t addr) {
    asm volatile("ldmatrix.sync.aligned.m8n8.x4.shared.b16 {%0,%1,%2,%3}, [%4];"
                 : "=r"(r[0]), "=r"(r[1]), "=r"(r[2]), "=r"(r[3]) : "r"(addr));
}

__device__ __forceinline__ void mma16816(float* d, const uint32_t* a,
                                         uint32_t b0, uint32_t b1) {
    asm volatile("mma.sync.aligned.m16n8k16.row.col.f32.f16.f16.f32 "
                 "{%0,%1,%2,%3}, {%4,%5,%6,%7}, {%8,%9}, {%0,%1,%2,%3};"
                 : "+f"(d[0]), "+f"(d[1]), "+f"(d[2]), "+f"(d[3])
                 : "r"(a[0]), "r"(a[1]), "r"(a[2]), "r"(a[3]), "r"(b0), "r"(b1));
}

__device__ __forceinline__ uint32_t pack2h(fp16 a, fp16 b) {
    __half2 t; t.x = a; t.y = b;
    return *reinterpret_cast<uint32_t*>(&t);
}

// ---------------------------------------------------------------------------
// hgemm<OUTMODE>: C[M,N] = alpha * A[M,K] * B[N,K]^T, A,B single fp16.
//   OUTMODE 0: fp32 C (alpha applied).  OUTMODE 2: single fp16 C.
// CTA tile 128x128x32, 256 threads (8 warps, 4x2, warptile 32x64),
// 3-stage cp.async pipeline, 16KB/stage (48KB total -> 2+ CTAs/SM).
// 64B rows; swizzle col16' = col16 ^ ((row>>1)&3): conflict-free ldmatrix.
// ---------------------------------------------------------------------------
#define GBK 32
#define STAGE_BYTES 16384
#define T_B 8192
#define HG_SMEM (3 * STAGE_BYTES)

template <int OUTMODE>
__global__ __launch_bounds__(256, 2)
void hgemm(const fp16* __restrict__ A, const fp16* __restrict__ B,
           float* __restrict__ Cf, fp16* __restrict__ Ch,
           int K, int ldC, float alpha,
           size_t strA, size_t strB, size_t strC)
{
    extern __shared__ __align__(128) char smem[];
    const uint32_t sb = smem_u32(smem);

    const int tid  = threadIdx.x;
    const int lane = tid & 31;
    const int wid  = tid >> 5;
    const int wm   = wid & 3;
    const int wn   = wid >> 2;

    const size_t bz = blockIdx.z;
    A += bz * strA;
    B += bz * strB;
    const int row0 = blockIdx.y * 128;
    const int col0 = blockIdx.x * 128;

    // 512 16B-chunks per tile type; 2 per thread per type.
    auto load_stage = [&](int s, int kiter) {
        const int k0 = kiter * GBK;
        const uint32_t stb = sb + s * STAGE_BYTES;
#pragma unroll
        for (int i = 0; i < 2; i++) {
            const int c    = tid + i * 256;
            const int row  = c >> 2;              // 0..127
            const int c16  = c & 3;               // 0..3 (16B col)
            const uint32_t soff =
                (uint32_t)(row * 64 + (((c16 ^ ((row >> 1) & 3)) & 3) << 4));
            const size_t goffA = (size_t)(row0 + row) * K + k0 + c16 * 8;
            const size_t goffB = (size_t)(col0 + row) * K + k0 + c16 * 8;
            cp_async16(stb + soff,       A + goffA);
            cp_async16(stb + T_B + soff, B + goffB);
        }
    };

    const int lr16 = lane & 15;
    const int lhi  = lane >> 4;
    int arow[2], brow[4];
#pragma unroll
    for (int mt = 0; mt < 2; mt++) arow[mt] = wm * 32 + mt * 16 + lr16;
#pragma unroll
    for (int np = 0; np < 4; np++) brow[np] = wn * 64 + np * 16 + lr16;

    auto smaddr = [&](int row, int cb) -> uint32_t {
        return (uint32_t)(row * 64 + (((cb ^ ((row >> 1) & 3)) & 3) << 4));
    };

    float acc[2][8][4];
#pragma unroll
    for (int a = 0; a < 2; a++)
#pragma unroll
        for (int b = 0; b < 8; b++)
#pragma unroll
            for (int r = 0; r < 4; r++) acc[a][b][r] = 0.f;

    const int niter = K / GBK;

    load_stage(0, 0); CP_COMMIT();
    load_stage(1, 1); CP_COMMIT();
    CP_WAIT1();
    __syncthreads();

    int s = 0, pf = 2;
    for (int it = 0; it < niter; ++it) {
        const uint32_t stb = sb + s * STAGE_BYTES;
#pragma unroll
        for (int kk = 0; kk < 2; kk++) {
            const int cb = kk * 2 + lhi;          // 0..3
            uint32_t a[2][4], b[4][4];
#pragma unroll
            for (int mt = 0; mt < 2; mt++)
                ldm_x4(a[mt], stb + smaddr(arow[mt], cb));
#pragma unroll
            for (int np = 0; np < 4; np++)
                ldm_x4(b[np], stb + T_B + smaddr(brow[np], cb));
#pragma unroll
            for (int np = 0; np < 4; np++)
#pragma unroll
                for (int mt = 0; mt < 2; mt++)
#pragma unroll
                    for (int sub = 0; sub < 2; sub++)
                        mma16816(acc[mt][np * 2 + sub], a[mt],
                                 b[np][sub], b[np][sub + 2]);
        }
        if (it + 2 < niter) {
            load_stage(pf, it + 2);
            CP_COMMIT();
            CP_WAIT1();
        } else {
            CP_WAIT0();
        }
        __syncthreads();
        s  = (s  == 2) ? 0 : s  + 1;
        pf = (pf == 2) ? 0 : pf + 1;
    }

    const int gi = lane >> 2;
    const int ti = lane & 3;
#pragma unroll
    for (int mt = 0; mt < 2; mt++) {
#pragma unroll
        for (int nt = 0; nt < 8; nt++) {
            const int col = col0 + wn * 64 + nt * 8 + ti * 2;
#pragma unroll
            for (int h = 0; h < 2; h++) {
                const size_t row = row0 + wm * 32 + mt * 16 + gi + h * 8;
                const float v0 = acc[mt][nt][h * 2 + 0] * alpha;
                const float v1 = acc[mt][nt][h * 2 + 1] * alpha;
                const size_t off = (strC * bz) + row * ldC + col;
                if (OUTMODE == 0) {
                    float2 f2; f2.x = v0; f2.y = v1;
                    *reinterpret_cast<float2*>(Cf + off) = f2;
                } else {
                    *reinterpret_cast<uint32_t*>(Ch + off) =
                        pack2h(__float2half_rn(v0), __float2half_rn(v1));
                }
            }
        }
    }
}

// ---------------------------------------------------------------------------
// conv: fp32 -> single fp16 (4 elems/thread)
// ---------------------------------------------------------------------------
__global__ __launch_bounds__(256)
void conv_kernel(const float* __restrict__ src, fp16* __restrict__ dst, int n4)
{
    const int i = blockIdx.x * 256 + threadIdx.x;
    if (i >= n4) return;
    float4 v = reinterpret_cast<const float4*>(src)[i];
    uint2 ph;
    ph.x = pack2h(__float2half_rn(v.x), __float2half_rn(v.y));
    ph.y = pack2h(__float2half_rn(v.z), __float2half_rn(v.w));
    reinterpret_cast<uint2*>(dst)[i] = ph;
}

// weights: fp32 -> single fp16, all 4 in one launch (grid.z selects)
struct WPtrs { const float* src[4]; fp16* h; };
__global__ __launch_bounds__(256)
void conv_w_kernel(WPtrs p, int n4)
{
    const int z = blockIdx.z;
    const int i = blockIdx.x * 256 + threadIdx.x;
    if (i >= n4) return;
    const size_t wstr = (size_t)DMODEL * DMODEL / 4;   // in uint2 units
    float4 v = reinterpret_cast<const float4*>(p.src[z])[i];
    uint2 ph;
    ph.x = pack2h(__float2half_rn(v.x), __float2half_rn(v.y));
    ph.y = pack2h(__float2half_rn(v.z), __float2half_rn(v.w));
    reinterpret_cast<uint2*>(p.h)[z * wstr + i] = ph;
}

// ---------------------------------------------------------------------------
// fp16 transpose per batch: dst[v][s] = src[s][v]
// ---------------------------------------------------------------------------
__global__ __launch_bounds__(256)
void transpose_h(const fp16* __restrict__ src, fp16* __restrict__ dst)
{
    __shared__ fp16 t[32][33];
    const fp16* s = src + (size_t)blockIdx.z * SEQ * DMODEL;
    fp16*       o = dst + (size_t)blockIdx.z * SEQ * DMODEL;
    const int s0 = blockIdx.x * 32;
    const int v0 = blockIdx.y * 32;
    const int tx = threadIdx.x & 31, ty = threadIdx.x >> 5;
#pragma unroll
    for (int r = 0; r < 4; r++)
        t[ty + r * 8][tx] = s[(size_t)(s0 + ty + r * 8) * DMODEL + v0 + tx];
    __syncthreads();
#pragma unroll
    for (int r = 0; r < 4; r++)
        o[(size_t)(v0 + ty + r * 8) * SEQ + s0 + tx] = t[tx][ty + r * 8];
}

// ---------------------------------------------------------------------------
// softmax row (2048) fp32 -> P single fp16
// ---------------------------------------------------------------------------
__global__ __launch_bounds__(256)
void softmax_kernel(const float* __restrict__ S, fp16* __restrict__ Ph)
{
    const size_t r0 = (size_t)blockIdx.x * SEQ;
    const float* row = S + r0;
    const int tid = threadIdx.x;

    float4 v0 = reinterpret_cast<const float4*>(row)[tid];
    float4 v1 = reinterpret_cast<const float4*>(row)[tid + 256];

    float m = fmaxf(fmaxf(fmaxf(v0.x, v0.y), fmaxf(v0.z, v0.w)),
                    fmaxf(fmaxf(v1.x, v1.y), fmaxf(v1.z, v1.w)));
    __shared__ float red[8];
#pragma unroll
    for (int o = 16; o > 0; o >>= 1)
        m = fmaxf(m, __shfl_xor_sync(0xffffffffu, m, o));
    if ((tid & 31) == 0) red[tid >> 5] = m;
    __syncthreads();
    m = red[0];
#pragma unroll
    for (int w = 1; w < 8; w++) m = fmaxf(m, red[w]);
    __syncthreads();

    v0.x = __expf(v0.x - m); v0.y = __expf(v0.y - m);
    v0.z = __expf(v0.z - m); v0.w = __expf(v0.w - m);
    v1.x = __expf(v1.x - m); v1.y = __expf(v1.y - m);
    v1.z = __expf(v1.z - m); v1.w = __expf(v1.w - m);

    float sum = (v0.x + v0.y + v0.z + v0.w) + (v1.x + v1.y + v1.z + v1.w);
#pragma unroll
    for (int o = 16; o > 0; o >>= 1)
        sum += __shfl_xor_sync(0xffffffffu, sum, o);
    if ((tid & 31) == 0) red[tid >> 5] = sum;
    __syncthreads();
    sum = red[0];
#pragma unroll
    for (int w = 1; w < 8; w++) sum += red[w];
    const float inv = 1.0f / sum;

    auto emit = [&](float4 v, int idx) {
        uint2 ph;
        ph.x = pack2h(__float2half_rn(v.x * inv), __float2half_rn(v.y * inv));
        ph.y = pack2h(__float2half_rn(v.z * inv), __float2half_rn(v.w * inv));
        reinterpret_cast<uint2*>(Ph + r0)[idx] = ph;
    };
    emit(v0, tid);
    emit(v1, tid + 256);
}

// ---------------------------------------------------------------------------
// Launch
// ---------------------------------------------------------------------------
extern "C" void kernel_launch(void* const* d_in, const int* in_sizes, int n_in,
                              void* d_out, int out_size)
{
    const float* x  = (const float*)d_in[0];
    float* out = (float*)d_out;

    fp16 *xh, *wh, *Qh, *Kh, *Vh, *Vth, *Ph, *Ch;
    float* S;
    cudaGetSymbolAddress((void**)&xh,  g_xh);
    cudaGetSymbolAddress((void**)&wh,  g_wh);
    cudaGetSymbolAddress((void**)&Qh,  g_Qh);
    cudaGetSymbolAddress((void**)&Kh,  g_Kh);
    cudaGetSymbolAddress((void**)&Vh,  g_Vh);
    cudaGetSymbolAddress((void**)&Vth, g_Vth);
    cudaGetSymbolAddress((void**)&S,   g_S);
    cudaGetSymbolAddress((void**)&Ph,  g_Ph);
    cudaGetSymbolAddress((void**)&Ch,  g_Ch);

    cudaFuncSetAttribute(hgemm<0>, cudaFuncAttributeMaxDynamicSharedMemorySize, HG_SMEM);
    cudaFuncSetAttribute(hgemm<2>, cudaFuncAttributeMaxDynamicSharedMemorySize, HG_SMEM);

    const dim3 blk(256);
    const size_t WSTR = (size_t)DMODEL * DMODEL;

    // #0: convert x -> single fp16
    conv_kernel<<<MTOT * DMODEL / 1024, blk>>>(x, xh, MTOT * DMODEL / 4);

    // #1: convert all 4 weights -> single fp16
    {
        WPtrs p;
        p.src[0] = (const float*)d_in[1];
        p.src[1] = (const float*)d_in[2];
        p.src[2] = (const float*)d_in[3];
        p.src[3] = (const float*)d_in[4];
        p.h = wh;
        dim3 g(DMODEL * DMODEL / 1024, 1, 4);
        conv_w_kernel<<<g, blk>>>(p, DMODEL * DMODEL / 4);
    }

    // #2-#4: projections -> single fp16 Q/K/V
    {
        dim3 grid(DMODEL / 128, MTOT / 128, 1);
        hgemm<2><<<grid, blk, HG_SMEM>>>(xh, wh + 0 * WSTR, nullptr, Qh,
                                         DMODEL, DMODEL, 1.f, 0, 0, 0);
        hgemm<2><<<grid, blk, HG_SMEM>>>(xh, wh + 1 * WSTR, nullptr, Kh,
                                         DMODEL, DMODEL, 1.f, 0, 0, 0);
        hgemm<2><<<grid, blk, HG_SMEM>>>(xh, wh + 2 * WSTR, nullptr, Vh,
                                         DMODEL, DMODEL, 1.f, 0, 0, 0);
    }

    // #5: S = Q K^T / 32 (fp32)
    {
        dim3 grid(SEQ / 128, SEQ / 128, BATCH);
        hgemm<0><<<grid, blk, HG_SMEM>>>(Qh, Kh, S, nullptr,
                                         DMODEL, SEQ, 0.03125f,
                                         (size_t)SEQ * DMODEL,
                                         (size_t)SEQ * DMODEL,
                                         (size_t)SEQ * SEQ);
    }

    // #6: V transpose
    {
        dim3 g(SEQ / 32, DMODEL / 32, BATCH);
        transpose_h<<<g, blk>>>(Vh, Vth);
    }

    // #7: softmax -> P single fp16
    softmax_kernel<<<MTOT, blk>>>(S, Ph);

    // #8: ctx = P Vt^T -> single fp16  (K = SEQ)
    {
        dim3 grid(DMODEL / 128, SEQ / 128, BATCH);
        hgemm<2><<<grid, blk, HG_SMEM>>>(Ph, Vth, nullptr, Ch,
                                         SEQ, DMODEL, 1.f,
                                         (size_t)SEQ * SEQ,
                                         (size_t)DMODEL * SEQ,
                                         (size_t)SEQ * DMODEL);
    }

    // #9: out = ctx wo^T (fp32)
    {
        dim3 grid(DMODEL / 128, MTOT / 128, 1);
        hgemm<0><<<grid, blk, HG_SMEM>>>(Ch, wh + 3 * WSTR, out, nullptr,
                                         DMODEL, DMODEL, 1.f, 0, 0, 0);
    }
}